// round 3
// baseline (speedup 1.0000x reference)
#include <cuda_runtime.h>
#include <math.h>

// B=512, T=256, F=64, N=128
#define BT 131072

typedef unsigned long long u64;

// Scratch (device globals)
__device__ float g_xz1[134217728];   // [BT,1024] e1/d2 xz
__device__ float g_xz2[67108864];    // [BT, 512] e2 xz
__device__ float g_h1 [33554432];    // [BT, 256] e1 / d2 output
__device__ float g_hd1[16777216];    // [BT, 128] d1 output
__device__ float g_z  [65536];       // [B, 128]
__device__ float g_xzd1[262144];     // [B, 512]

__device__ __forceinline__ float sigm(float x) {
    return __fdividef(1.0f, 1.0f + __expf(-x));
}

// ---- packed f32x2 helpers (Blackwell) ----
__device__ __forceinline__ u64 pk2(float x, float y) {
    u64 r; asm("mov.b64 %0, {%1, %2};" : "=l"(r) : "f"(x), "f"(y)); return r;
}
__device__ __forceinline__ float2 upk(u64 v) {
    float2 r; asm("mov.b64 {%0, %1}, %2;" : "=f"(r.x), "=f"(r.y) : "l"(v)); return r;
}
__device__ __forceinline__ void fma2(u64 &d, u64 a, u64 b) {
    asm("fma.rn.f32x2 %0, %1, %2, %0;" : "+l"(d) : "l"(a), "l"(b));
}

// ---------------------------------------------------------------------------
// SGEMM + bias. A values stored DUPLICATED in smem as (a,a) float2 so the
// inner loop is pure LDS.128 + FFMA2 (no broadcast movs).
// C[M,N] = A[M,K] @ W[K,N] + bias[N]. 128x128 tile, BK=8, 256 thr, 8x8/thr.
// ---------------------------------------------------------------------------
__global__ __launch_bounds__(256) void sgemm_bias(
    const float* __restrict__ A, const float* __restrict__ W,
    const float* __restrict__ bias, float* __restrict__ C,
    int M, int N, int K, int ldc)
{
    __shared__ float2 As[2][8][128];   // duplicated (a,a)
    __shared__ float  Bs[2][8][128];

    const int tid = threadIdx.x;
    const int bm = blockIdx.y * 128;
    const int bn = blockIdx.x * 128;
    const int m0 = (tid / 16) * 8;
    const int n0 = (tid % 16) * 8;
    const int arow = tid / 2,  acol = (tid % 2) * 4;
    const int brow = tid / 32, bcol = (tid % 32) * 4;

    u64 acc[8][4];
    #pragma unroll
    for (int i = 0; i < 8; i++)
        #pragma unroll
        for (int jp = 0; jp < 4; jp++) acc[i][jp] = 0ull;

    // prologue
    float4 a4 = *(const float4*)(A + (size_t)(bm + arow) * K + acol);
    float4 b4 = make_float4(0.f, 0.f, 0.f, 0.f);
    if (bn + bcol < N) b4 = *(const float4*)(W + (size_t)brow * N + bn + bcol);
    As[0][acol + 0][arow] = make_float2(a4.x, a4.x);
    As[0][acol + 1][arow] = make_float2(a4.y, a4.y);
    As[0][acol + 2][arow] = make_float2(a4.z, a4.z);
    As[0][acol + 3][arow] = make_float2(a4.w, a4.w);
    *(float4*)&Bs[0][brow][bcol] = b4;
    __syncthreads();

    const int nk = K / 8;
    for (int kt = 0; kt < nk; kt++) {
        const int buf = kt & 1;
        if (kt + 1 < nk) {
            const int k0 = (kt + 1) * 8;
            a4 = *(const float4*)(A + (size_t)(bm + arow) * K + k0 + acol);
            b4 = make_float4(0.f, 0.f, 0.f, 0.f);
            if (bn + bcol < N)
                b4 = *(const float4*)(W + (size_t)(k0 + brow) * N + bn + bcol);
        }
        #pragma unroll
        for (int kk = 0; kk < 8; kk++) {
            const ulonglong2* ap = (const ulonglong2*)&As[buf][kk][m0];
            ulonglong2 t0 = ap[0], t1 = ap[1], t2 = ap[2], t3 = ap[3];
            u64 aa[8] = {t0.x, t0.y, t1.x, t1.y, t2.x, t2.y, t3.x, t3.y};
            const u64* bp = (const u64*)&Bs[buf][kk][n0];
            u64 bb[4] = {bp[0], bp[1], bp[2], bp[3]};
            #pragma unroll
            for (int i = 0; i < 8; i++) {
                fma2(acc[i][0], aa[i], bb[0]);
                fma2(acc[i][1], aa[i], bb[1]);
                fma2(acc[i][2], aa[i], bb[2]);
                fma2(acc[i][3], aa[i], bb[3]);
            }
        }
        if (kt + 1 < nk) {
            const int nb = buf ^ 1;
            As[nb][acol + 0][arow] = make_float2(a4.x, a4.x);
            As[nb][acol + 1][arow] = make_float2(a4.y, a4.y);
            As[nb][acol + 2][arow] = make_float2(a4.z, a4.z);
            As[nb][acol + 3][arow] = make_float2(a4.w, a4.w);
            *(float4*)&Bs[nb][brow][bcol] = b4;
        }
        __syncthreads();
    }

    #pragma unroll
    for (int i = 0; i < 8; i++) {
        size_t row = (size_t)(bm + m0 + i) * ldc;
        #pragma unroll
        for (int jp = 0; jp < 4; jp++) {
            float2 v = upk(acc[i][jp]);
            int n = bn + n0 + jp * 2;
            if (n < N)     C[row + n]     = v.x + bias[n];
            if (n + 1 < N) C[row + n + 1] = v.y + bias[n + 1];
        }
    }
}

// ---------------------------------------------------------------------------
// LSTM recurrence. 256 threads/CTA (2 warps/SMSP), grid (64 chunks, 2 dirs).
// 8 batch rows per CTA; thread owns column j and NB=HU/32 rows.
// U gate-pair-packed ulonglong2 ((Ui,Uf),(Ug,Uo)): KSMEM rows smem, rest regs.
// h stored per [buf][row][k] as duplicated (h,h) u64: broadcast LDS.64 reads,
// contiguous conflict-free writes. xz prefetched one step ahead.
// ---------------------------------------------------------------------------
template<int HU, int KSMEM, bool SEQ>
__global__ __launch_bounds__(256, 1)
void lstm_kernel(const float* __restrict__ xz, size_t strideB, size_t strideT,
                 const float* __restrict__ Uf, const float* __restrict__ Ub,
                 float* __restrict__ out, int ldo, int T)
{
    constexpr int NB   = HU / 32;       // 4 for HU=128, 2 for HU=64
    constexpr int REGK = HU - KSMEM;

    extern __shared__ char smraw[];
    ulonglong2* Us = (ulonglong2*)smraw;                         // [KSMEM*HU]
    u64*        hS = (u64*)(smraw + (size_t)KSMEM * HU * 16);    // [2][8][HU]

    const int tid = threadIdx.x;
    const int j   = tid % HU;
    const int bg  = tid / HU;           // 0..1 (HU=128) / 0..3 (HU=64)
    const int dir = blockIdx.y;
    const int b0  = blockIdx.x * 8 + bg * NB;

    const float* U    = dir ? Ub : Uf;
    const float* xzd  = xz + (size_t)dir * (4 * HU);
    float*       outd = out + dir * HU;

    for (int idx = tid; idx < KSMEM * HU; idx += 256) {
        int k = idx / HU, jj = idx % HU;
        const float* ur = U + (size_t)k * (4 * HU) + jj;
        Us[idx] = make_ulonglong2(pk2(ur[0], ur[HU]), pk2(ur[2 * HU], ur[3 * HU]));
    }
    ulonglong2 wreg[REGK > 0 ? REGK : 1];
    #pragma unroll
    for (int r = 0; r < REGK; r++) {
        const float* ur = U + (size_t)(KSMEM + r) * (4 * HU) + j;
        wreg[r] = make_ulonglong2(pk2(ur[0], ur[HU]), pk2(ur[2 * HU], ur[3 * HU]));
    }
    for (int idx = tid; idx < 2 * 8 * HU; idx += 256) hS[idx] = 0ull;
    __syncthreads();

    float c[NB];
    #pragma unroll
    for (int b = 0; b < NB; b++) c[b] = 0.f;
    int cur = 0;

    // prefetch xz for t=0
    float xn[NB][4];
    {
        const int tt = dir ? (T - 1) : 0;
        #pragma unroll
        for (int b = 0; b < NB; b++) {
            const float* xp = xzd + (size_t)(b0 + b) * strideB + (size_t)tt * strideT + j;
            xn[b][0] = xp[0]; xn[b][1] = xp[HU];
            xn[b][2] = xp[2 * HU]; xn[b][3] = xp[3 * HU];
        }
    }

    for (int t = 0; t < T; t++) {
        const int tt = dir ? (T - 1 - t) : t;

        u64 aif[NB], ago[NB];
        #pragma unroll
        for (int b = 0; b < NB; b++) {
            aif[b] = pk2(xn[b][0], xn[b][1]);
            ago[b] = pk2(xn[b][2], xn[b][3]);
        }
        if (t + 1 < T) {  // prefetch next step; overlaps k-loop
            const int tn = dir ? (T - 2 - t) : (t + 1);
            #pragma unroll
            for (int b = 0; b < NB; b++) {
                const float* xp = xzd + (size_t)(b0 + b) * strideB + (size_t)tn * strideT + j;
                xn[b][0] = xp[0]; xn[b][1] = xp[HU];
                xn[b][2] = xp[2 * HU]; xn[b][3] = xp[3 * HU];
            }
        }

        const u64* hrow = hS + cur * (8 * HU) + bg * NB * HU;  // rows owned by this group

        #pragma unroll 4
        for (int k = 0; k < KSMEM; k++) {
            ulonglong2 w = Us[k * HU + j];
            #pragma unroll
            for (int b = 0; b < NB; b++) {
                u64 hd = hrow[b * HU + k];          // broadcast
                fma2(aif[b], hd, w.x);
                fma2(ago[b], hd, w.y);
            }
        }
        #pragma unroll
        for (int r = 0; r < REGK; r++) {
            const int k = KSMEM + r;
            ulonglong2 w = wreg[r];
            #pragma unroll
            for (int b = 0; b < NB; b++) {
                u64 hd = hrow[b * HU + k];
                fma2(aif[b], hd, w.x);
                fma2(ago[b], hd, w.y);
            }
        }

        float hn[NB];
        #pragma unroll
        for (int b = 0; b < NB; b++) {
            float2 vif = upk(aif[b]);
            float2 vgo = upk(ago[b]);
            float ig = sigm(vif.x);
            float fg = sigm(vif.y);
            float gg = fmaxf(vgo.x, 0.f);
            float og = sigm(vgo.y);
            c[b] = fg * c[b] + ig * gg;
            hn[b] = og * fmaxf(c[b], 0.f);
        }

        if (SEQ) {
            #pragma unroll
            for (int b = 0; b < NB; b++)
                outd[((size_t)(b0 + b) * T + tt) * ldo + j] = hn[b];
        } else if (t == T - 1) {
            #pragma unroll
            for (int b = 0; b < NB; b++)
                outd[(size_t)(b0 + b) * ldo + j] = hn[b];
        }

        // publish duplicated h for next step (contiguous 8B stores, no conflicts)
        u64* hw = hS + (cur ^ 1) * (8 * HU) + bg * NB * HU;
        #pragma unroll
        for (int b = 0; b < NB; b++)
            hw[b * HU + j] = pk2(hn[b], hn[b]);

        __syncthreads();
        cur ^= 1;
    }
}

// ---------------------------------------------------------------------------
extern "C" void kernel_launch(void* const* d_in, const int* in_sizes, int n_in,
                              void* d_out, int out_size)
{
    const float* x    = (const float*)d_in[0];
    const float* e1fW = (const float*)d_in[1];
    const float* e1fU = (const float*)d_in[2];
    const float* e1fb = (const float*)d_in[3];
    const float* e1bW = (const float*)d_in[4];
    const float* e1bU = (const float*)d_in[5];
    const float* e1bb = (const float*)d_in[6];
    const float* e2fW = (const float*)d_in[7];
    const float* e2fU = (const float*)d_in[8];
    const float* e2fb = (const float*)d_in[9];
    const float* e2bW = (const float*)d_in[10];
    const float* e2bU = (const float*)d_in[11];
    const float* e2bb = (const float*)d_in[12];
    const float* d1fW = (const float*)d_in[13];
    const float* d1fU = (const float*)d_in[14];
    const float* d1fb = (const float*)d_in[15];
    const float* d1bW = (const float*)d_in[16];
    const float* d1bU = (const float*)d_in[17];
    const float* d1bb = (const float*)d_in[18];
    const float* d2fW = (const float*)d_in[19];
    const float* d2fU = (const float*)d_in[20];
    const float* d2fb = (const float*)d_in[21];
    const float* d2bW = (const float*)d_in[22];
    const float* d2bU = (const float*)d_in[23];
    const float* d2bb = (const float*)d_in[24];
    const float* Wd   = (const float*)d_in[25];
    const float* bd   = (const float*)d_in[26];

    float *xz1, *xz2, *h1, *hd1, *z, *xzd1;
    cudaGetSymbolAddress((void**)&xz1,  g_xz1);
    cudaGetSymbolAddress((void**)&xz2,  g_xz2);
    cudaGetSymbolAddress((void**)&h1,   g_h1);
    cudaGetSymbolAddress((void**)&hd1,  g_hd1);
    cudaGetSymbolAddress((void**)&z,    g_z);
    cudaGetSymbolAddress((void**)&xzd1, g_xzd1);

    // smem: HU=128/KSMEM=100: 100*128*16 + 2*8*128*8 = 221184
    //       HU=64 /KSMEM=64 :  64*64*16  + 2*8*64*8  =  73728
    const int SMEM128 = 100 * 128 * 16 + 2 * 8 * 128 * 8;
    const int SMEM64  =  64 *  64 * 16 + 2 * 8 *  64 * 8;
    cudaFuncSetAttribute(lstm_kernel<128, 100, true>,
                         cudaFuncAttributeMaxDynamicSharedMemorySize, SMEM128);
    cudaFuncSetAttribute(lstm_kernel<64, 64, true>,
                         cudaFuncAttributeMaxDynamicSharedMemorySize, SMEM64);
    cudaFuncSetAttribute(lstm_kernel<64, 64, false>,
                         cudaFuncAttributeMaxDynamicSharedMemorySize, SMEM64);

    const int T = 256;

    // e1
    sgemm_bias<<<dim3(4, 1024), 256>>>(x, e1fW, e1fb, xz1,       BT, 512, 64, 1024);
    sgemm_bias<<<dim3(4, 1024), 256>>>(x, e1bW, e1bb, xz1 + 512, BT, 512, 64, 1024);
    lstm_kernel<128, 100, true><<<dim3(64, 2), 256, SMEM128>>>(
        xz1, (size_t)T * 1024, 1024, e1fU, e1bU, h1, 256, T);

    // e2
    sgemm_bias<<<dim3(2, 1024), 256>>>(h1, e2fW, e2fb, xz2,       BT, 256, 256, 512);
    sgemm_bias<<<dim3(2, 1024), 256>>>(h1, e2bW, e2bb, xz2 + 256, BT, 256, 256, 512);
    lstm_kernel<64, 64, false><<<dim3(64, 2), 256, SMEM64>>>(
        xz2, (size_t)T * 512, 512, e2fU, e2bU, z, 128, T);

    // d1 (z broadcast over T -> xz computed once per batch row)
    sgemm_bias<<<dim3(2, 4), 256>>>(z, d1fW, d1fb, xzd1,       512, 256, 128, 512);
    sgemm_bias<<<dim3(2, 4), 256>>>(z, d1bW, d1bb, xzd1 + 256, 512, 256, 128, 512);
    lstm_kernel<64, 64, true><<<dim3(64, 2), 256, SMEM64>>>(
        xzd1, 512, 0, d1fU, d1bU, hd1, 128, T);

    // d2
    sgemm_bias<<<dim3(4, 1024), 256>>>(hd1, d2fW, d2fb, xz1,       BT, 512, 128, 1024);
    sgemm_bias<<<dim3(4, 1024), 256>>>(hd1, d2bW, d2bb, xz1 + 512, BT, 512, 128, 1024);
    lstm_kernel<128, 100, true><<<dim3(64, 2), 256, SMEM128>>>(
        xz1, (size_t)T * 1024, 1024, d2fU, d2bU, h1, 256, T);

    // dense
    sgemm_bias<<<dim3(1, 1024), 256>>>(h1, Wd, bd, (float*)d_out, BT, 64, 256, 64);
}

// round 4
// speedup vs baseline: 1.0442x; 1.0442x over previous
#include <cuda_runtime.h>
#include <math.h>

// B=512, T=256, F=64, N=128
#define BT 131072

typedef unsigned long long u64;

// Scratch (device globals)
__device__ float g_xz1[134217728];   // [BT,1024] e1/d2 xz
__device__ float g_xz2[67108864];    // [BT, 512] e2 xz
__device__ float g_h1 [33554432];    // [BT, 256] e1 / d2 output
__device__ float g_hd1[16777216];    // [BT, 128] d1 output
__device__ float g_z  [65536];       // [B, 128]
__device__ float g_xzd1[262144];     // [B, 512]

__device__ __forceinline__ float sigm(float x) {
    return __fdividef(1.0f, 1.0f + __expf(-x));
}

// ---- packed f32x2 helpers ----
__device__ __forceinline__ u64 pk2(float x, float y) {
    u64 r; asm("mov.b64 %0, {%1, %2};" : "=l"(r) : "f"(x), "f"(y)); return r;
}
__device__ __forceinline__ float2 upk(u64 v) {
    float2 r; asm("mov.b64 {%0, %1}, %2;" : "=f"(r.x), "=f"(r.y) : "l"(v)); return r;
}
__device__ __forceinline__ void fma2(u64 &d, u64 a, u64 b) {
    asm("fma.rn.f32x2 %0, %1, %2, %0;" : "+l"(d) : "l"(a), "l"(b));
}

// ---------------------------------------------------------------------------
// SGEMM + bias, FFMA2. As duplicated (a,a) in smem -> pure LDS+FFMA2 inner
// loop. Register-capped for 2 CTAs/SM. 128x128 tile, BK=8, 256 thr, 8x8/thr.
// ---------------------------------------------------------------------------
__global__ __launch_bounds__(256, 2) void sgemm_bias(
    const float* __restrict__ A, const float* __restrict__ W,
    const float* __restrict__ bias, float* __restrict__ C,
    int M, int N, int K, int ldc)
{
    __shared__ float2 As[2][8][128];   // duplicated (a,a)
    __shared__ float  Bs[2][8][128];

    const int tid = threadIdx.x;
    const int bm = blockIdx.y * 128;
    const int bn = blockIdx.x * 128;
    const int m0 = (tid / 16) * 8;
    const int n0 = (tid % 16) * 8;
    const int arow = tid / 2,  acol = (tid % 2) * 4;
    const int brow = tid / 32, bcol = (tid % 32) * 4;

    u64 acc[8][4];
    #pragma unroll
    for (int i = 0; i < 8; i++)
        #pragma unroll
        for (int jp = 0; jp < 4; jp++) acc[i][jp] = 0ull;

    float4 a4 = *(const float4*)(A + (size_t)(bm + arow) * K + acol);
    float4 b4 = make_float4(0.f, 0.f, 0.f, 0.f);
    if (bn + bcol < N) b4 = *(const float4*)(W + (size_t)brow * N + bn + bcol);
    As[0][acol + 0][arow] = make_float2(a4.x, a4.x);
    As[0][acol + 1][arow] = make_float2(a4.y, a4.y);
    As[0][acol + 2][arow] = make_float2(a4.z, a4.z);
    As[0][acol + 3][arow] = make_float2(a4.w, a4.w);
    *(float4*)&Bs[0][brow][bcol] = b4;
    __syncthreads();

    const int nk = K / 8;
    for (int kt = 0; kt < nk; kt++) {
        const int buf = kt & 1;
        if (kt + 1 < nk) {
            const int k0 = (kt + 1) * 8;
            a4 = *(const float4*)(A + (size_t)(bm + arow) * K + k0 + acol);
            b4 = make_float4(0.f, 0.f, 0.f, 0.f);
            if (bn + bcol < N)
                b4 = *(const float4*)(W + (size_t)(k0 + brow) * N + bn + bcol);
        }
        #pragma unroll
        for (int kk = 0; kk < 8; kk++) {
            const ulonglong2* bp = (const ulonglong2*)&Bs[buf][kk][n0];
            ulonglong2 b01 = bp[0], b23 = bp[1];
            const ulonglong2* ap = (const ulonglong2*)&As[buf][kk][m0];
            #pragma unroll
            for (int ih = 0; ih < 4; ih++) {
                ulonglong2 a2 = ap[ih];   // (a_{2ih},a_{2ih}),(a_{2ih+1},a_{2ih+1})
                fma2(acc[2*ih][0],   a2.x, b01.x);
                fma2(acc[2*ih][1],   a2.x, b01.y);
                fma2(acc[2*ih][2],   a2.x, b23.x);
                fma2(acc[2*ih][3],   a2.x, b23.y);
                fma2(acc[2*ih+1][0], a2.y, b01.x);
                fma2(acc[2*ih+1][1], a2.y, b01.y);
                fma2(acc[2*ih+1][2], a2.y, b23.x);
                fma2(acc[2*ih+1][3], a2.y, b23.y);
            }
        }
        if (kt + 1 < nk) {
            const int nb = buf ^ 1;
            As[nb][acol + 0][arow] = make_float2(a4.x, a4.x);
            As[nb][acol + 1][arow] = make_float2(a4.y, a4.y);
            As[nb][acol + 2][arow] = make_float2(a4.z, a4.z);
            As[nb][acol + 3][arow] = make_float2(a4.w, a4.w);
            *(float4*)&Bs[nb][brow][bcol] = b4;
        }
        __syncthreads();
    }

    #pragma unroll
    for (int i = 0; i < 8; i++) {
        size_t row = (size_t)(bm + m0 + i) * ldc;
        #pragma unroll
        for (int jp = 0; jp < 4; jp++) {
            float2 v = upk(acc[i][jp]);
            int n = bn + n0 + jp * 2;
            if (n < N)     C[row + n]     = v.x + bias[n];
            if (n + 1 < N) C[row + n + 1] = v.y + bias[n + 1];
        }
    }
}

// ---------------------------------------------------------------------------
// LSTM recurrence, gate-split. 256 threads, grid (64 chunks, 2 dirs).
// Thread = (col j, gate-pair gp, [row-half rh for HU=64]); owns NRT rows.
// Per k: 1 LDS.64 (w pair) + NRT/2 LDS.128 (broadcast dup'd h) + NRT FFMA2.
// gp1 computes (relu(g), sigm(o)), ships to gp0 via smem; gp0 owns c/h.
// U: KSMEM rows in smem as (k,gp,j)->u64, REGK rows in regs.
// h: [buf][rowpair][k] ulonglong2 of (dup h_2rp, dup h_2rp+1).
// ---------------------------------------------------------------------------
template<int HU, int KSMEM, bool SEQ, bool CONSTX>
__global__ __launch_bounds__(256, 1)
void lstm_kernel(const float* __restrict__ xz, size_t strideB, size_t strideT,
                 const float* __restrict__ Uf, const float* __restrict__ Ub,
                 float* __restrict__ out, int ldo, int T)
{
    constexpr int NRT  = (HU == 128) ? 8 : 4;   // rows per thread
    constexpr int NRP  = NRT / 2;
    constexpr int REGK = HU - KSMEM;

    extern __shared__ char smraw[];
    u64*        Us = (u64*)smraw;                                   // [KSMEM][2][HU]
    ulonglong2* hP = (ulonglong2*)(smraw + (size_t)KSMEM * 2 * HU * 8); // [2][4][HU]
    u64*        ex = (u64*)(hP + 2 * 4 * HU);                       // [8][HU]

    const int tid = threadIdx.x;
    const int j   = tid % HU;
    const int gp  = (tid / HU) & 1;
    const int rh  = tid / (2 * HU);   // 0 for HU=128; 0..1 for HU=64
    const int r0  = rh * NRT;
    const int dir = blockIdx.y;
    const int b0  = blockIdx.x * 8;

    const float* U    = dir ? Ub : Uf;
    const float* xzd  = xz + (size_t)dir * (4 * HU);
    float*       outd = out + dir * HU;

    // U -> smem (gate-pair packed)
    for (int idx = tid; idx < KSMEM * 2 * HU; idx += 256) {
        int k  = idx / (2 * HU);
        int g  = (idx / HU) & 1;
        int jj = idx % HU;
        const float* ur = U + (size_t)k * (4 * HU) + 2 * g * HU + jj;
        Us[idx] = pk2(ur[0], ur[HU]);
    }
    // U tail -> regs (this thread's (gp,j))
    u64 wreg[REGK > 0 ? REGK : 1];
    #pragma unroll
    for (int r = 0; r < REGK; r++) {
        const float* ur = U + (size_t)(KSMEM + r) * (4 * HU) + 2 * gp * HU + j;
        wreg[r] = pk2(ur[0], ur[HU]);
    }
    for (int idx = tid; idx < 2 * 4 * HU; idx += 256)
        hP[idx] = make_ulonglong2(0ull, 0ull);
    __syncthreads();

    float c[NRT];
    #pragma unroll
    for (int r = 0; r < NRT; r++) c[r] = 0.f;
    int cur = 0;

    // xz prefetch (this thread's gate pair, NRT rows)
    float xn[NRT][2];
    {
        const int tt = dir ? (T - 1) : 0;
        #pragma unroll
        for (int r = 0; r < NRT; r++) {
            const float* xp = xzd + (size_t)(b0 + r0 + r) * strideB
                              + (CONSTX ? 0 : (size_t)tt * strideT)
                              + 2 * gp * HU + j;
            xn[r][0] = xp[0]; xn[r][1] = xp[HU];
        }
    }

    for (int t = 0; t < T; t++) {
        const int tt = dir ? (T - 1 - t) : t;

        u64 acc[NRT];
        #pragma unroll
        for (int r = 0; r < NRT; r++) acc[r] = pk2(xn[r][0], xn[r][1]);

        if (!CONSTX && t + 1 < T) {    // prefetch next step, overlaps k-loop
            const int tn = dir ? (T - 2 - t) : (t + 1);
            #pragma unroll
            for (int r = 0; r < NRT; r++) {
                const float* xp = xzd + (size_t)(b0 + r0 + r) * strideB
                                  + (size_t)tn * strideT + 2 * gp * HU + j;
                xn[r][0] = xp[0]; xn[r][1] = xp[HU];
            }
        }

        const ulonglong2* hrow = hP + cur * (4 * HU) + (r0 / 2) * HU;
        const u64* wj = Us + gp * HU + j;

        #pragma unroll 8
        for (int k = 0; k < KSMEM; k++) {
            u64 w = wj[(size_t)k * 2 * HU];
            #pragma unroll
            for (int q = 0; q < NRP; q++) {
                ulonglong2 h2 = hrow[q * HU + k];   // broadcast
                fma2(acc[2 * q],     h2.x, w);
                fma2(acc[2 * q + 1], h2.y, w);
            }
        }
        #pragma unroll
        for (int r = 0; r < REGK; r++) {
            const int k = KSMEM + r;
            u64 w = wreg[r];
            #pragma unroll
            for (int q = 0; q < NRP; q++) {
                ulonglong2 h2 = hrow[q * HU + k];
                fma2(acc[2 * q],     h2.x, w);
                fma2(acc[2 * q + 1], h2.y, w);
            }
        }

        if (gp == 1) {   // (g,o): apply nonlinearities, ship to gp0
            #pragma unroll
            for (int r = 0; r < NRT; r++) {
                float2 v = upk(acc[r]);
                ex[(r0 + r) * HU + j] = pk2(fmaxf(v.x, 0.f), sigm(v.y));
            }
        }
        __syncthreads();
        if (gp == 0) {   // (i,f): combine, update c/h, publish
            float hn[NRT];
            #pragma unroll
            for (int r = 0; r < NRT; r++) {
                float2 v  = upk(acc[r]);
                float2 go = upk(ex[(r0 + r) * HU + j]);
                float ig = sigm(v.x), fg = sigm(v.y);
                c[r]  = fg * c[r] + ig * go.x;
                hn[r] = go.y * fmaxf(c[r], 0.f);
            }
            if (SEQ) {
                #pragma unroll
                for (int r = 0; r < NRT; r++)
                    outd[((size_t)(b0 + r0 + r) * T + tt) * ldo + j] = hn[r];
            } else if (t == T - 1) {
                #pragma unroll
                for (int r = 0; r < NRT; r++)
                    outd[(size_t)(b0 + r0 + r) * ldo + j] = hn[r];
            }
            ulonglong2* hw = hP + (cur ^ 1) * (4 * HU) + (r0 / 2) * HU + j;
            #pragma unroll
            for (int q = 0; q < NRP; q++)
                hw[q * HU] = make_ulonglong2(pk2(hn[2*q],   hn[2*q]),
                                             pk2(hn[2*q+1], hn[2*q+1]));
        }
        __syncthreads();
        cur ^= 1;
    }
}

// ---------------------------------------------------------------------------
extern "C" void kernel_launch(void* const* d_in, const int* in_sizes, int n_in,
                              void* d_out, int out_size)
{
    const float* x    = (const float*)d_in[0];
    const float* e1fW = (const float*)d_in[1];
    const float* e1fU = (const float*)d_in[2];
    const float* e1fb = (const float*)d_in[3];
    const float* e1bW = (const float*)d_in[4];
    const float* e1bU = (const float*)d_in[5];
    const float* e1bb = (const float*)d_in[6];
    const float* e2fW = (const float*)d_in[7];
    const float* e2fU = (const float*)d_in[8];
    const float* e2fb = (const float*)d_in[9];
    const float* e2bW = (const float*)d_in[10];
    const float* e2bU = (const float*)d_in[11];
    const float* e2bb = (const float*)d_in[12];
    const float* d1fW = (const float*)d_in[13];
    const float* d1fU = (const float*)d_in[14];
    const float* d1fb = (const float*)d_in[15];
    const float* d1bW = (const float*)d_in[16];
    const float* d1bU = (const float*)d_in[17];
    const float* d1bb = (const float*)d_in[18];
    const float* d2fW = (const float*)d_in[19];
    const float* d2fU = (const float*)d_in[20];
    const float* d2fb = (const float*)d_in[21];
    const float* d2bW = (const float*)d_in[22];
    const float* d2bU = (const float*)d_in[23];
    const float* d2bb = (const float*)d_in[24];
    const float* Wd   = (const float*)d_in[25];
    const float* bd   = (const float*)d_in[26];

    float *xz1, *xz2, *h1, *hd1, *z, *xzd1;
    cudaGetSymbolAddress((void**)&xz1,  g_xz1);
    cudaGetSymbolAddress((void**)&xz2,  g_xz2);
    cudaGetSymbolAddress((void**)&h1,   g_h1);
    cudaGetSymbolAddress((void**)&hd1,  g_hd1);
    cudaGetSymbolAddress((void**)&z,    g_z);
    cudaGetSymbolAddress((void**)&xzd1, g_xzd1);

    // smem: HU=128/KSMEM=96: 96*256*8 + 2*4*128*16 + 8*128*8 = 221184
    //       HU=64 /KSMEM=64: 64*128*8 + 2*4*64*16  + 8*64*8  =  77824
    const int SMEM128 = 96 * 2 * 128 * 8 + 2 * 4 * 128 * 16 + 8 * 128 * 8;
    const int SMEM64  = 64 * 2 *  64 * 8 + 2 * 4 *  64 * 16 + 8 *  64 * 8;
    cudaFuncSetAttribute(lstm_kernel<128, 96, true, false>,
                         cudaFuncAttributeMaxDynamicSharedMemorySize, SMEM128);
    cudaFuncSetAttribute(lstm_kernel<64, 64, false, false>,
                         cudaFuncAttributeMaxDynamicSharedMemorySize, SMEM64);
    cudaFuncSetAttribute(lstm_kernel<64, 64, true, true>,
                         cudaFuncAttributeMaxDynamicSharedMemorySize, SMEM64);

    const int T = 256;

    // e1
    sgemm_bias<<<dim3(4, 1024), 256>>>(x, e1fW, e1fb, xz1,       BT, 512, 64, 1024);
    sgemm_bias<<<dim3(4, 1024), 256>>>(x, e1bW, e1bb, xz1 + 512, BT, 512, 64, 1024);
    lstm_kernel<128, 96, true, false><<<dim3(64, 2), 256, SMEM128>>>(
        xz1, (size_t)T * 1024, 1024, e1fU, e1bU, h1, 256, T);

    // e2
    sgemm_bias<<<dim3(2, 1024), 256>>>(h1, e2fW, e2fb, xz2,       BT, 256, 256, 512);
    sgemm_bias<<<dim3(2, 1024), 256>>>(h1, e2bW, e2bb, xz2 + 256, BT, 256, 256, 512);
    lstm_kernel<64, 64, false, false><<<dim3(64, 2), 256, SMEM64>>>(
        xz2, (size_t)T * 512, 512, e2fU, e2bU, z, 128, T);

    // d1 (z broadcast over T -> xz computed once per batch row; CONSTX)
    sgemm_bias<<<dim3(2, 4), 256>>>(z, d1fW, d1fb, xzd1,       512, 256, 128, 512);
    sgemm_bias<<<dim3(2, 4), 256>>>(z, d1bW, d1bb, xzd1 + 256, 512, 256, 128, 512);
    lstm_kernel<64, 64, true, true><<<dim3(64, 2), 256, SMEM64>>>(
        xzd1, 512, 0, d1fU, d1bU, hd1, 128, T);

    // d2
    sgemm_bias<<<dim3(4, 1024), 256>>>(hd1, d2fW, d2fb, xz1,       BT, 512, 128, 1024);
    sgemm_bias<<<dim3(4, 1024), 256>>>(hd1, d2bW, d2bb, xz1 + 512, BT, 512, 128, 1024);
    lstm_kernel<128, 96, true, false><<<dim3(64, 2), 256, SMEM128>>>(
        xz1, (size_t)T * 1024, 1024, d2fU, d2bU, h1, 256, T);

    // dense
    sgemm_bias<<<dim3(1, 1024), 256>>>(h1, Wd, bd, (float*)d_out, BT, 64, 256, 64);
}

// round 6
// speedup vs baseline: 1.6726x; 1.6018x over previous
#include <cuda_runtime.h>
#include <cuda_bf16.h>
#include <math.h>
#include <stdint.h>

// B=512, T=256, F=64, N=128
#define BT 131072
typedef unsigned long long u64;
typedef unsigned int u32;

// Scratch (device globals)
__device__ float g_xz1[134217728];   // [BT,1024] e1/d2 xz
__device__ float g_xz2[67108864];    // [BT, 512] e2 xz
__device__ float g_h1 [33554432];    // [BT, 256] e1 / d2 output
__device__ float g_hd1[16777216];    // [BT, 128] d1 output
__device__ float g_z  [65536];       // [B, 128]
__device__ float g_xzd1[262144];     // [B, 512]

__device__ __forceinline__ float sigm(float x) {
    return __fdividef(1.0f, 1.0f + __expf(-x));
}

// ---- packed f32x2 helpers (LSTM) ----
__device__ __forceinline__ u64 pk2(float x, float y) {
    u64 r; asm("mov.b64 %0, {%1, %2};" : "=l"(r) : "f"(x), "f"(y)); return r;
}
__device__ __forceinline__ float2 upk(u64 v) {
    float2 r; asm("mov.b64 {%0, %1}, %2;" : "=f"(r.x), "=f"(r.y) : "l"(v)); return r;
}
__device__ __forceinline__ void fma2(u64 &d, u64 a, u64 b) {
    asm("fma.rn.f32x2 %0, %1, %2, %0;" : "+l"(d) : "l"(a), "l"(b));
}

// ---- HMMA helpers (baseline PTX, valid on sm_103 without 'a') ----
__device__ __forceinline__ u32 smem_u32(const void* p) {
    u32 a; asm("{ .reg .u64 t; cvta.to.shared.u64 t, %1; cvt.u32.u64 %0, t; }"
               : "=r"(a) : "l"(p));
    return a;
}
__device__ __forceinline__ u32 pkbf(float a, float b) {
    __nv_bfloat162 t = __floats2bfloat162_rn(a, b);
    return *reinterpret_cast<u32*>(&t);
}
__device__ __forceinline__ void ldsm4(u32 &r0, u32 &r1, u32 &r2, u32 &r3, u32 a) {
    asm volatile("ldmatrix.sync.aligned.m8n8.x4.shared.b16 {%0,%1,%2,%3}, [%4];"
                 : "=r"(r0), "=r"(r1), "=r"(r2), "=r"(r3) : "r"(a));
}
__device__ __forceinline__ void ldsm4t(u32 &r0, u32 &r1, u32 &r2, u32 &r3, u32 a) {
    asm volatile("ldmatrix.sync.aligned.m8n8.x4.trans.shared.b16 {%0,%1,%2,%3}, [%4];"
                 : "=r"(r0), "=r"(r1), "=r"(r2), "=r"(r3) : "r"(a));
}
__device__ __forceinline__ void mma16816(float* c, const u32* a, const u32* b) {
    asm volatile("mma.sync.aligned.m16n8k16.row.col.f32.bf16.bf16.f32 "
                 "{%0,%1,%2,%3}, {%4,%5,%6,%7}, {%8,%9}, {%0,%1,%2,%3};"
                 : "+f"(c[0]), "+f"(c[1]), "+f"(c[2]), "+f"(c[3])
                 : "r"(a[0]), "r"(a[1]), "r"(a[2]), "r"(a[3]), "r"(b[0]), "r"(b[1]));
}

// ---------------------------------------------------------------------------
// Split-precision bf16 HMMA GEMM: C[M,N] = A[M,K] @ W[K,N] + bias
// fp32 = hi(bf16) + lo(bf16); product = hi*hi + hi*lo + lo*hi  (lo*lo dropped,
// <=2^-16 rel). Tile 128 x NT, K chunks of 32 fp32 (-> 64 bf16 in smem).
// Warp grid WM x WN. Requires M%128==0, N%NT==0, K%32==0.
// ---------------------------------------------------------------------------
template<int NT, int WM, int WN>
__global__ __launch_bounds__(256, 2)
void hmma_gemm(const float* __restrict__ A, const float* __restrict__ W,
               const float* __restrict__ bias, float* __restrict__ C,
               int K, int Nw, int ldc)
{
    constexpr int PA = 144;            // A row pitch bytes (64 bf16 + 16 pad)
    constexpr int PB = NT * 2 + 16;    // B row pitch bytes
    constexpr int MW    = 128 / WM;    // warp m-tile
    constexpr int NWT   = NT / WN;     // warp n-tile
    constexpr int MFRAG = MW / 16;
    constexpr int NFRAG = NWT / 8;
    constexpr int BV    = NT / 8;      // B floats per thread per chunk

    __shared__ char smA[128 * PA];     // [m][kk] kk: 0..31 hi, 32..63 lo
    __shared__ char smB[64 * PB];      // [kk][n] rows: 0..31 hi, 32..63 lo

    const int tid  = threadIdx.x;
    const int wid  = tid >> 5, lane = tid & 31;
    const int bm   = blockIdx.y * 128, bn = blockIdx.x * NT;
    const int wm   = (wid / WN) * MW,  wn = (wid % WN) * NWT;
    const u32 sA   = smem_u32(smA), sB = smem_u32(smB);

    float acc[MFRAG][NFRAG][4];
    #pragma unroll
    for (int i = 0; i < MFRAG; i++)
        #pragma unroll
        for (int j = 0; j < NFRAG; j++)
            #pragma unroll
            for (int q = 0; q < 4; q++) acc[i][j][q] = 0.f;

    const int arow = tid >> 1, akq = (tid & 1) * 16;
    const int bkk  = tid >> 3, bn0 = (tid & 7) * BV;

    float av[16], bv[BV];
    {   // prologue: chunk 0
        const float* ap = A + (size_t)(bm + arow) * K + akq;
        #pragma unroll
        for (int i = 0; i < 16; i += 4) *(float4*)(av + i) = *(const float4*)(ap + i);
        const float* bp = W + (size_t)bkk * Nw + bn + bn0;
        #pragma unroll
        for (int i = 0; i < BV; i += 4) *(float4*)(bv + i) = *(const float4*)(bp + i);
    }

    const int nch = K / 32;
    for (int ch = 0; ch < nch; ch++) {
        // ---- convert + store to smem ----
        {
            char* arow_p = smA + arow * PA;
            #pragma unroll
            for (int i = 0; i < 16; i += 2) {
                float x0 = av[i], x1 = av[i + 1];
                float h0 = __bfloat162float(__float2bfloat16_rn(x0));
                float h1 = __bfloat162float(__float2bfloat16_rn(x1));
                *(u32*)(arow_p + 2 * (akq + i))      = pkbf(h0, h1);
                *(u32*)(arow_p + 64 + 2 * (akq + i)) = pkbf(x0 - h0, x1 - h1);
            }
            char* bhi = smB + bkk * PB;
            char* blo = smB + (bkk + 32) * PB;
            #pragma unroll
            for (int i = 0; i < BV; i += 2) {
                float x0 = bv[i], x1 = bv[i + 1];
                float h0 = __bfloat162float(__float2bfloat16_rn(x0));
                float h1 = __bfloat162float(__float2bfloat16_rn(x1));
                *(u32*)(bhi + 2 * (bn0 + i)) = pkbf(h0, h1);
                *(u32*)(blo + 2 * (bn0 + i)) = pkbf(x0 - h0, x1 - h1);
            }
        }
        __syncthreads();

        // prefetch next chunk (overlaps mma below)
        if (ch + 1 < nch) {
            const int k0 = (ch + 1) * 32;
            const float* ap = A + (size_t)(bm + arow) * K + k0 + akq;
            #pragma unroll
            for (int i = 0; i < 16; i += 4) *(float4*)(av + i) = *(const float4*)(ap + i);
            const float* bp = W + (size_t)(k0 + bkk) * Nw + bn + bn0;
            #pragma unroll
            for (int i = 0; i < BV; i += 4) *(float4*)(bv + i) = *(const float4*)(bp + i);
        }

        // ---- 3 split terms x 2 k16-steps ----
        #pragma unroll
        for (int term = 0; term < 3; term++) {
            const int aB = (term == 2) ? 1 : 0;   // (hi,hi),(hi,lo),(lo,hi)
            const int bB = (term == 1) ? 1 : 0;
            #pragma unroll
            for (int s = 0; s < 2; s++) {
                const u32 kbA = (u32)(aB * 32 + s * 16) * 2;
                const int krB = bB * 32 + s * 16;
                u32 a[MFRAG][4];
                #pragma unroll
                for (int mf = 0; mf < MFRAG; mf++)
                    ldsm4(a[mf][0], a[mf][1], a[mf][2], a[mf][3],
                          sA + (u32)(wm + mf * 16 + (lane & 15)) * PA
                             + kbA + ((lane >> 4) << 4));
                u32 b[NFRAG][2];
                #pragma unroll
                for (int np = 0; np < NFRAG / 2; np++) {
                    u32 r0, r1, r2, r3;
                    ldsm4t(r0, r1, r2, r3,
                           sB + (u32)(krB + (lane & 15)) * PB
                              + 2 * (u32)(wn + np * 16 + ((lane >> 4) << 3)));
                    b[2 * np][0] = r0; b[2 * np][1] = r1;
                    b[2 * np + 1][0] = r2; b[2 * np + 1][1] = r3;
                }
                #pragma unroll
                for (int mf = 0; mf < MFRAG; mf++)
                    #pragma unroll
                    for (int nf = 0; nf < NFRAG; nf++)
                        mma16816(acc[mf][nf], a[mf], b[nf]);
            }
        }
        __syncthreads();
    }

    // ---- epilogue: bias + store ----
    #pragma unroll
    for (int mf = 0; mf < MFRAG; mf++) {
        #pragma unroll
        for (int nf = 0; nf < NFRAG; nf++) {
            const int r0 = bm + wm + mf * 16 + (lane >> 2);
            const int cc = bn + wn + nf * 8 + (lane & 3) * 2;
            const float b0 = bias[cc], b1 = bias[cc + 1];
            float2 v0 = make_float2(acc[mf][nf][0] + b0, acc[mf][nf][1] + b1);
            float2 v1 = make_float2(acc[mf][nf][2] + b0, acc[mf][nf][3] + b1);
            *(float2*)&C[(size_t)r0 * ldc + cc]       = v0;
            *(float2*)&C[(size_t)(r0 + 8) * ldc + cc] = v1;
        }
    }
}

// ---------------------------------------------------------------------------
// LSTM recurrence (R2 version — best measured). 128 thr, grid (64 chunks, 2 dirs).
// ---------------------------------------------------------------------------
template<int HU, int KSMEM, bool SEQ>
__global__ __launch_bounds__(128, 1)
void lstm_kernel(const float* __restrict__ xz, size_t strideB, size_t strideT,
                 const float* __restrict__ Uf, const float* __restrict__ Ub,
                 float* __restrict__ out, int ldo, int T)
{
    constexpr int NB   = HU / 16;
    constexpr int REGK = HU - KSMEM;

    extern __shared__ char smraw[];
    ulonglong2* Us = (ulonglong2*)smraw;                         // [KSMEM*HU]
    float2*     hS = (float2*)(smraw + (size_t)KSMEM * HU * 16); // [2][HU*8]

    const int tid = threadIdx.x;
    const int j   = tid % HU;
    const int bg  = tid / HU;
    const int dir = blockIdx.y;
    const int b0  = blockIdx.x * 8 + bg * NB;

    const float* U    = dir ? Ub : Uf;
    const float* xzd  = xz + (size_t)dir * (4 * HU);
    float*       outd = out + dir * HU;

    for (int idx = tid; idx < KSMEM * HU; idx += 128) {
        int k = idx / HU, jj = idx % HU;
        const float* ur = U + (size_t)k * (4 * HU) + jj;
        Us[idx] = make_ulonglong2(pk2(ur[0], ur[HU]), pk2(ur[2 * HU], ur[3 * HU]));
    }
    ulonglong2 wreg[REGK > 0 ? REGK : 1];
    #pragma unroll
    for (int r = 0; r < REGK; r++) {
        const float* ur = U + (size_t)(KSMEM + r) * (4 * HU) + j;
        wreg[r] = make_ulonglong2(pk2(ur[0], ur[HU]), pk2(ur[2 * HU], ur[3 * HU]));
    }
    for (int idx = tid; idx < HU * 8; idx += 128) hS[idx] = make_float2(0.f, 0.f);
    __syncthreads();

    float c[NB];
    #pragma unroll
    for (int b = 0; b < NB; b++) c[b] = 0.f;
    int cur = 0;

    float xn[NB][4];
    {
        const int tt = dir ? (T - 1) : 0;
        #pragma unroll
        for (int b = 0; b < NB; b++) {
            const float* xp = xzd + (size_t)(b0 + b) * strideB + (size_t)tt * strideT + j;
            xn[b][0] = xp[0]; xn[b][1] = xp[HU];
            xn[b][2] = xp[2 * HU]; xn[b][3] = xp[3 * HU];
        }
    }

    for (int t = 0; t < T; t++) {
        const int tt = dir ? (T - 1 - t) : t;

        u64 aif[NB], ago[NB];
        #pragma unroll
        for (int b = 0; b < NB; b++) {
            aif[b] = pk2(xn[b][0], xn[b][1]);
            ago[b] = pk2(xn[b][2], xn[b][3]);
        }
        if (t + 1 < T) {
            const int tn = dir ? (T - 2 - t) : (t + 1);
            #pragma unroll
            for (int b = 0; b < NB; b++) {
                const float* xp = xzd + (size_t)(b0 + b) * strideB + (size_t)tn * strideT + j;
                xn[b][0] = xp[0]; xn[b][1] = xp[HU];
                xn[b][2] = xp[2 * HU]; xn[b][3] = xp[3 * HU];
            }
        }

        const float2* hrow = hS + cur * (HU * 8);

        #pragma unroll 4
        for (int k = 0; k < KSMEM; k++) {
            ulonglong2 w = Us[k * HU + j];
            const ulonglong2* hp = (const ulonglong2*)(hrow + k * 8 + bg * NB);
            #pragma unroll
            for (int q = 0; q < NB / 2; q++) {
                ulonglong2 h2 = hp[q];
                fma2(aif[2 * q],     h2.x, w.x);
                fma2(ago[2 * q],     h2.x, w.y);
                fma2(aif[2 * q + 1], h2.y, w.x);
                fma2(ago[2 * q + 1], h2.y, w.y);
            }
        }
        #pragma unroll
        for (int r = 0; r < REGK; r++) {
            const int k = KSMEM + r;
            ulonglong2 w = wreg[r];
            const ulonglong2* hp = (const ulonglong2*)(hrow + k * 8 + bg * NB);
            #pragma unroll
            for (int q = 0; q < NB / 2; q++) {
                ulonglong2 h2 = hp[q];
                fma2(aif[2 * q],     h2.x, w.x);
                fma2(ago[2 * q],     h2.x, w.y);
                fma2(aif[2 * q + 1], h2.y, w.x);
                fma2(ago[2 * q + 1], h2.y, w.y);
            }
        }

        float hn[NB];
        #pragma unroll
        for (int b = 0; b < NB; b++) {
            float2 vif = upk(aif[b]);
            float2 vgo = upk(ago[b]);
            float ig = sigm(vif.x);
            float fg = sigm(vif.y);
            float gg = fmaxf(vgo.x, 0.f);
            float og = sigm(vgo.y);
            c[b] = fg * c[b] + ig * gg;
            hn[b] = og * fmaxf(c[b], 0.f);
        }

        if (SEQ) {
            #pragma unroll
            for (int b = 0; b < NB; b++)
                outd[((size_t)(b0 + b) * T + tt) * ldo + j] = hn[b];
        } else if (t == T - 1) {
            #pragma unroll
            for (int b = 0; b < NB; b++)
                outd[(size_t)(b0 + b) * ldo + j] = hn[b];
        }

        float2* hw = hS + (cur ^ 1) * (HU * 8) + j * 8 + bg * NB;
        #pragma unroll
        for (int q = 0; q < NB / 2; q++)
            *(float4*)(hw + 2 * q) =
                make_float4(hn[2 * q], hn[2 * q], hn[2 * q + 1], hn[2 * q + 1]);

        __syncthreads();
        cur ^= 1;
    }
}

// ---------------------------------------------------------------------------
extern "C" void kernel_launch(void* const* d_in, const int* in_sizes, int n_in,
                              void* d_out, int out_size)
{
    const float* x    = (const float*)d_in[0];
    const float* e1fW = (const float*)d_in[1];
    const float* e1fU = (const float*)d_in[2];
    const float* e1fb = (const float*)d_in[3];
    const float* e1bW = (const float*)d_in[4];
    const float* e1bU = (const float*)d_in[5];
    const float* e1bb = (const float*)d_in[6];
    const float* e2fW = (const float*)d_in[7];
    const float* e2fU = (const float*)d_in[8];
    const float* e2fb = (const float*)d_in[9];
    const float* e2bW = (const float*)d_in[10];
    const float* e2bU = (const float*)d_in[11];
    const float* e2bb = (const float*)d_in[12];
    const float* d1fW = (const float*)d_in[13];
    const float* d1fU = (const float*)d_in[14];
    const float* d1fb = (const float*)d_in[15];
    const float* d1bW = (const float*)d_in[16];
    const float* d1bU = (const float*)d_in[17];
    const float* d1bb = (const float*)d_in[18];
    const float* d2fW = (const float*)d_in[19];
    const float* d2fU = (const float*)d_in[20];
    const float* d2fb = (const float*)d_in[21];
    const float* d2bW = (const float*)d_in[22];
    const float* d2bU = (const float*)d_in[23];
    const float* d2bb = (const float*)d_in[24];
    const float* Wd   = (const float*)d_in[25];
    const float* bd   = (const float*)d_in[26];

    float *xz1, *xz2, *h1, *hd1, *z, *xzd1;
    cudaGetSymbolAddress((void**)&xz1,  g_xz1);
    cudaGetSymbolAddress((void**)&xz2,  g_xz2);
    cudaGetSymbolAddress((void**)&h1,   g_h1);
    cudaGetSymbolAddress((void**)&hd1,  g_hd1);
    cudaGetSymbolAddress((void**)&z,    g_z);
    cudaGetSymbolAddress((void**)&xzd1, g_xzd1);

    const int SMEM128 = 100 * 128 * 16 + 2 * 128 * 8 * 8;
    const int SMEM64  =  64 *  64 * 16 + 2 *  64 * 8 * 8;
    cudaFuncSetAttribute(lstm_kernel<128, 100, true>,
                         cudaFuncAttributeMaxDynamicSharedMemorySize, SMEM128);
    cudaFuncSetAttribute(lstm_kernel<64, 64, true>,
                         cudaFuncAttributeMaxDynamicSharedMemorySize, SMEM64);
    cudaFuncSetAttribute(lstm_kernel<64, 64, false>,
                         cudaFuncAttributeMaxDynamicSharedMemorySize, SMEM64);

    const int T = 256;

    // e1: xz = x @ W + b   (K=64, N=512)
    hmma_gemm<128, 2, 4><<<dim3(4, 1024), 256>>>(x, e1fW, e1fb, xz1,       64, 512, 1024);
    hmma_gemm<128, 2, 4><<<dim3(4, 1024), 256>>>(x, e1bW, e1bb, xz1 + 512, 64, 512, 1024);
    lstm_kernel<128, 100, true><<<dim3(64, 2), 128, SMEM128>>>(
        xz1, (size_t)T * 1024, 1024, e1fU, e1bU, h1, 256, T);

    // e2 (K=256, N=256)
    hmma_gemm<128, 2, 4><<<dim3(2, 1024), 256>>>(h1, e2fW, e2fb, xz2,       256, 256, 512);
    hmma_gemm<128, 2, 4><<<dim3(2, 1024), 256>>>(h1, e2bW, e2bb, xz2 + 256, 256, 256, 512);
    lstm_kernel<64, 64, false><<<dim3(64, 2), 128, SMEM64>>>(
        xz2, (size_t)T * 512, 512, e2fU, e2bU, z, 128, T);

    // d1 (z broadcast over T -> xz once per batch row; M=512, K=128, N=256)
    hmma_gemm<128, 2, 4><<<dim3(2, 4), 256>>>(z, d1fW, d1fb, xzd1,       128, 256, 512);
    hmma_gemm<128, 2, 4><<<dim3(2, 4), 256>>>(z, d1bW, d1bb, xzd1 + 256, 128, 256, 512);
    lstm_kernel<64, 64, true><<<dim3(64, 2), 128, SMEM64>>>(
        xzd1, 512, 0, d1fU, d1bU, hd1, 128, T);

    // d2 (K=128, N=512)
    hmma_gemm<128, 2, 4><<<dim3(4, 1024), 256>>>(hd1, d2fW, d2fb, xz1,       128, 512, 1024);
    hmma_gemm<128, 2, 4><<<dim3(4, 1024), 256>>>(hd1, d2bW, d2bb, xz1 + 512, 128, 512, 1024);
    lstm_kernel<128, 100, true><<<dim3(64, 2), 128, SMEM128>>>(
        xz1, (size_t)T * 1024, 1024, d2fU, d2bU, h1, 256, T);

    // dense (K=256, N=64)
    hmma_gemm<64, 4, 2><<<dim3(1, 1024), 256>>>(h1, Wd, bd, (float*)d_out, 256, 64, 64);
}

// round 7
// speedup vs baseline: 1.6775x; 1.0029x over previous
#include <cuda_runtime.h>
#include <cuda_bf16.h>
#include <math.h>
#include <stdint.h>

// B=512, T=256, F=64, N=128
#define BT 131072
typedef unsigned long long u64;
typedef unsigned int u32;

// Scratch (device globals)
__device__ float g_xz1[134217728];   // [BT,1024] e1/d2 xz
__device__ float g_xz2[67108864];    // [BT, 512] e2 xz
__device__ float g_h1 [33554432];    // [BT, 256] e1 / d2 output
__device__ float g_hd1[16777216];    // [BT, 128] d1 output
__device__ float g_z  [65536];       // [B, 128]
__device__ float g_xzd1[262144];     // [B, 512]

__device__ __forceinline__ float sigm(float x) {
    return __fdividef(1.0f, 1.0f + __expf(-x));
}

// ---- packed f32x2 helpers (LSTM) ----
__device__ __forceinline__ u64 pk2(float x, float y) {
    u64 r; asm("mov.b64 %0, {%1, %2};" : "=l"(r) : "f"(x), "f"(y)); return r;
}
__device__ __forceinline__ float2 upk(u64 v) {
    float2 r; asm("mov.b64 {%0, %1}, %2;" : "=f"(r.x), "=f"(r.y) : "l"(v)); return r;
}
__device__ __forceinline__ void fma2(u64 &d, u64 a, u64 b) {
    asm("fma.rn.f32x2 %0, %1, %2, %0;" : "+l"(d) : "l"(a), "l"(b));
}

// ---- HMMA helpers (baseline PTX, valid on sm_103 without 'a') ----
__device__ __forceinline__ u32 smem_u32(const void* p) {
    u32 a; asm("{ .reg .u64 t; cvta.to.shared.u64 t, %1; cvt.u32.u64 %0, t; }"
               : "=r"(a) : "l"(p));
    return a;
}
__device__ __forceinline__ u32 pkbf(float a, float b) {
    __nv_bfloat162 t = __floats2bfloat162_rn(a, b);
    return *reinterpret_cast<u32*>(&t);
}
__device__ __forceinline__ void ldsm4(u32 &r0, u32 &r1, u32 &r2, u32 &r3, u32 a) {
    asm volatile("ldmatrix.sync.aligned.m8n8.x4.shared.b16 {%0,%1,%2,%3}, [%4];"
                 : "=r"(r0), "=r"(r1), "=r"(r2), "=r"(r3) : "r"(a));
}
__device__ __forceinline__ void ldsm4t(u32 &r0, u32 &r1, u32 &r2, u32 &r3, u32 a) {
    asm volatile("ldmatrix.sync.aligned.m8n8.x4.trans.shared.b16 {%0,%1,%2,%3}, [%4];"
                 : "=r"(r0), "=r"(r1), "=r"(r2), "=r"(r3) : "r"(a));
}
__device__ __forceinline__ void mma16816(float* c, const u32* a, const u32* b) {
    asm volatile("mma.sync.aligned.m16n8k16.row.col.f32.bf16.bf16.f32 "
                 "{%0,%1,%2,%3}, {%4,%5,%6,%7}, {%8,%9}, {%0,%1,%2,%3};"
                 : "+f"(c[0]), "+f"(c[1]), "+f"(c[2]), "+f"(c[3])
                 : "r"(a[0]), "r"(a[1]), "r"(a[2]), "r"(a[3]), "r"(b[0]), "r"(b[1]));
}

// ---------------------------------------------------------------------------
// Split-precision bf16 HMMA GEMM: C[M,N] = A[M,K] @ W[K,N] + bias
// fp32 = hi(bf16) + lo(bf16); product = hi*hi + hi*lo + lo*hi  (lo*lo dropped,
// <=2^-16 rel). Tile 128 x NT, K chunks of 32 fp32 (-> 64 bf16 in smem).
// Warp grid WM x WN. Requires M%128==0, N%NT==0, K%32==0.
// ---------------------------------------------------------------------------
template<int NT, int WM, int WN>
__global__ __launch_bounds__(256, 2)
void hmma_gemm(const float* __restrict__ A, const float* __restrict__ W,
               const float* __restrict__ bias, float* __restrict__ C,
               int K, int Nw, int ldc)
{
    constexpr int PA = 144;            // A row pitch bytes (64 bf16 + 16 pad)
    constexpr int PB = NT * 2 + 16;    // B row pitch bytes
    constexpr int MW    = 128 / WM;    // warp m-tile
    constexpr int NWT   = NT / WN;     // warp n-tile
    constexpr int MFRAG = MW / 16;
    constexpr int NFRAG = NWT / 8;
    constexpr int BV    = NT / 8;      // B floats per thread per chunk

    __shared__ char smA[128 * PA];     // [m][kk] kk: 0..31 hi, 32..63 lo
    __shared__ char smB[64 * PB];      // [kk][n] rows: 0..31 hi, 32..63 lo

    const int tid  = threadIdx.x;
    const int wid  = tid >> 5, lane = tid & 31;
    const int bm   = blockIdx.y * 128, bn = blockIdx.x * NT;
    const int wm   = (wid / WN) * MW,  wn = (wid % WN) * NWT;
    const u32 sA   = smem_u32(smA), sB = smem_u32(smB);

    float acc[MFRAG][NFRAG][4];
    #pragma unroll
    for (int i = 0; i < MFRAG; i++)
        #pragma unroll
        for (int j = 0; j < NFRAG; j++)
            #pragma unroll
            for (int q = 0; q < 4; q++) acc[i][j][q] = 0.f;

    const int arow = tid >> 1, akq = (tid & 1) * 16;
    const int bkk  = tid >> 3, bn0 = (tid & 7) * BV;

    float av[16], bv[BV];
    {   // prologue: chunk 0
        const float* ap = A + (size_t)(bm + arow) * K + akq;
        #pragma unroll
        for (int i = 0; i < 16; i += 4) *(float4*)(av + i) = *(const float4*)(ap + i);
        const float* bp = W + (size_t)bkk * Nw + bn + bn0;
        #pragma unroll
        for (int i = 0; i < BV; i += 4) *(float4*)(bv + i) = *(const float4*)(bp + i);
    }

    const int nch = K / 32;
    for (int ch = 0; ch < nch; ch++) {
        // ---- convert + store to smem ----
        {
            char* arow_p = smA + arow * PA;
            #pragma unroll
            for (int i = 0; i < 16; i += 2) {
                float x0 = av[i], x1 = av[i + 1];
                float h0 = __bfloat162float(__float2bfloat16_rn(x0));
                float h1 = __bfloat162float(__float2bfloat16_rn(x1));
                *(u32*)(arow_p + 2 * (akq + i))      = pkbf(h0, h1);
                *(u32*)(arow_p + 64 + 2 * (akq + i)) = pkbf(x0 - h0, x1 - h1);
            }
            char* bhi = smB + bkk * PB;
            char* blo = smB + (bkk + 32) * PB;
            #pragma unroll
            for (int i = 0; i < BV; i += 2) {
                float x0 = bv[i], x1 = bv[i + 1];
                float h0 = __bfloat162float(__float2bfloat16_rn(x0));
                float h1 = __bfloat162float(__float2bfloat16_rn(x1));
                *(u32*)(bhi + 2 * (bn0 + i)) = pkbf(h0, h1);
                *(u32*)(blo + 2 * (bn0 + i)) = pkbf(x0 - h0, x1 - h1);
            }
        }
        __syncthreads();

        // prefetch next chunk (overlaps mma below)
        if (ch + 1 < nch) {
            const int k0 = (ch + 1) * 32;
            const float* ap = A + (size_t)(bm + arow) * K + k0 + akq;
            #pragma unroll
            for (int i = 0; i < 16; i += 4) *(float4*)(av + i) = *(const float4*)(ap + i);
            const float* bp = W + (size_t)(k0 + bkk) * Nw + bn + bn0;
            #pragma unroll
            for (int i = 0; i < BV; i += 4) *(float4*)(bv + i) = *(const float4*)(bp + i);
        }

        // ---- 3 split terms x 2 k16-steps ----
        #pragma unroll
        for (int term = 0; term < 3; term++) {
            const int aB = (term == 2) ? 1 : 0;   // (hi,hi),(hi,lo),(lo,hi)
            const int bB = (term == 1) ? 1 : 0;
            #pragma unroll
            for (int s = 0; s < 2; s++) {
                const u32 kbA = (u32)(aB * 32 + s * 16) * 2;
                const int krB = bB * 32 + s * 16;
                u32 a[MFRAG][4];
                #pragma unroll
                for (int mf = 0; mf < MFRAG; mf++)
                    ldsm4(a[mf][0], a[mf][1], a[mf][2], a[mf][3],
                          sA + (u32)(wm + mf * 16 + (lane & 15)) * PA
                             + kbA + ((lane >> 4) << 4));
                u32 b[NFRAG][2];
                #pragma unroll
                for (int np = 0; np < NFRAG / 2; np++) {
                    u32 r0, r1, r2, r3;
                    ldsm4t(r0, r1, r2, r3,
                           sB + (u32)(krB + (lane & 15)) * PB
                              + 2 * (u32)(wn + np * 16 + ((lane >> 4) << 3)));
                    b[2 * np][0] = r0; b[2 * np][1] = r1;
                    b[2 * np + 1][0] = r2; b[2 * np + 1][1] = r3;
                }
                #pragma unroll
                for (int mf = 0; mf < MFRAG; mf++)
                    #pragma unroll
                    for (int nf = 0; nf < NFRAG; nf++)
                        mma16816(acc[mf][nf], a[mf], b[nf]);
            }
        }
        __syncthreads();
    }

    // ---- epilogue: bias + store ----
    #pragma unroll
    for (int mf = 0; mf < MFRAG; mf++) {
        #pragma unroll
        for (int nf = 0; nf < NFRAG; nf++) {
            const int r0 = bm + wm + mf * 16 + (lane >> 2);
            const int cc = bn + wn + nf * 8 + (lane & 3) * 2;
            const float b0 = bias[cc], b1 = bias[cc + 1];
            float2 v0 = make_float2(acc[mf][nf][0] + b0, acc[mf][nf][1] + b1);
            float2 v1 = make_float2(acc[mf][nf][2] + b0, acc[mf][nf][3] + b1);
            *(float2*)&C[(size_t)r0 * ldc + cc]       = v0;
            *(float2*)&C[(size_t)(r0 + 8) * ldc + cc] = v1;
        }
    }
}

// ---------------------------------------------------------------------------
// LSTM recurrence (R2 version — best measured). 128 thr, grid (64 chunks, 2 dirs).
// ---------------------------------------------------------------------------
template<int HU, int KSMEM, bool SEQ>
__global__ __launch_bounds__(128, 1)
void lstm_kernel(const float* __restrict__ xz, size_t strideB, size_t strideT,
                 const float* __restrict__ Uf, const float* __restrict__ Ub,
                 float* __restrict__ out, int ldo, int T)
{
    constexpr int NB   = HU / 16;
    constexpr int REGK = HU - KSMEM;

    extern __shared__ char smraw[];
    ulonglong2* Us = (ulonglong2*)smraw;                         // [KSMEM*HU]
    float2*     hS = (float2*)(smraw + (size_t)KSMEM * HU * 16); // [2][HU*8]

    const int tid = threadIdx.x;
    const int j   = tid % HU;
    const int bg  = tid / HU;
    const int dir = blockIdx.y;
    const int b0  = blockIdx.x * 8 + bg * NB;

    const float* U    = dir ? Ub : Uf;
    const float* xzd  = xz + (size_t)dir * (4 * HU);
    float*       outd = out + dir * HU;

    for (int idx = tid; idx < KSMEM * HU; idx += 128) {
        int k = idx / HU, jj = idx % HU;
        const float* ur = U + (size_t)k * (4 * HU) + jj;
        Us[idx] = make_ulonglong2(pk2(ur[0], ur[HU]), pk2(ur[2 * HU], ur[3 * HU]));
    }
    ulonglong2 wreg[REGK > 0 ? REGK : 1];
    #pragma unroll
    for (int r = 0; r < REGK; r++) {
        const float* ur = U + (size_t)(KSMEM + r) * (4 * HU) + j;
        wreg[r] = make_ulonglong2(pk2(ur[0], ur[HU]), pk2(ur[2 * HU], ur[3 * HU]));
    }
    for (int idx = tid; idx < HU * 8; idx += 128) hS[idx] = make_float2(0.f, 0.f);
    __syncthreads();

    float c[NB];
    #pragma unroll
    for (int b = 0; b < NB; b++) c[b] = 0.f;
    int cur = 0;

    float xn[NB][4];
    {
        const int tt = dir ? (T - 1) : 0;
        #pragma unroll
        for (int b = 0; b < NB; b++) {
            const float* xp = xzd + (size_t)(b0 + b) * strideB + (size_t)tt * strideT + j;
            xn[b][0] = xp[0]; xn[b][1] = xp[HU];
            xn[b][2] = xp[2 * HU]; xn[b][3] = xp[3 * HU];
        }
    }

    for (int t = 0; t < T; t++) {
        const int tt = dir ? (T - 1 - t) : t;

        u64 aif[NB], ago[NB];
        #pragma unroll
        for (int b = 0; b < NB; b++) {
            aif[b] = pk2(xn[b][0], xn[b][1]);
            ago[b] = pk2(xn[b][2], xn[b][3]);
        }
        if (t + 1 < T) {
            const int tn = dir ? (T - 2 - t) : (t + 1);
            #pragma unroll
            for (int b = 0; b < NB; b++) {
                const float* xp = xzd + (size_t)(b0 + b) * strideB + (size_t)tn * strideT + j;
                xn[b][0] = xp[0]; xn[b][1] = xp[HU];
                xn[b][2] = xp[2 * HU]; xn[b][3] = xp[3 * HU];
            }
        }

        const float2* hrow = hS + cur * (HU * 8);

        #pragma unroll 4
        for (int k = 0; k < KSMEM; k++) {
            ulonglong2 w = Us[k * HU + j];
            const ulonglong2* hp = (const ulonglong2*)(hrow + k * 8 + bg * NB);
            #pragma unroll
            for (int q = 0; q < NB / 2; q++) {
                ulonglong2 h2 = hp[q];
                fma2(aif[2 * q],     h2.x, w.x);
                fma2(ago[2 * q],     h2.x, w.y);
                fma2(aif[2 * q + 1], h2.y, w.x);
                fma2(ago[2 * q + 1], h2.y, w.y);
            }
        }
        #pragma unroll
        for (int r = 0; r < REGK; r++) {
            const int k = KSMEM + r;
            ulonglong2 w = wreg[r];
            const ulonglong2* hp = (const ulonglong2*)(hrow + k * 8 + bg * NB);
            #pragma unroll
            for (int q = 0; q < NB / 2; q++) {
                ulonglong2 h2 = hp[q];
                fma2(aif[2 * q],     h2.x, w.x);
                fma2(ago[2 * q],     h2.x, w.y);
                fma2(aif[2 * q + 1], h2.y, w.x);
                fma2(ago[2 * q + 1], h2.y, w.y);
            }
        }

        float hn[NB];
        #pragma unroll
        for (int b = 0; b < NB; b++) {
            float2 vif = upk(aif[b]);
            float2 vgo = upk(ago[b]);
            float ig = sigm(vif.x);
            float fg = sigm(vif.y);
            float gg = fmaxf(vgo.x, 0.f);
            float og = sigm(vgo.y);
            c[b] = fg * c[b] + ig * gg;
            hn[b] = og * fmaxf(c[b], 0.f);
        }

        if (SEQ) {
            #pragma unroll
            for (int b = 0; b < NB; b++)
                outd[((size_t)(b0 + b) * T + tt) * ldo + j] = hn[b];
        } else if (t == T - 1) {
            #pragma unroll
            for (int b = 0; b < NB; b++)
                outd[(size_t)(b0 + b) * ldo + j] = hn[b];
        }

        float2* hw = hS + (cur ^ 1) * (HU * 8) + j * 8 + bg * NB;
        #pragma unroll
        for (int q = 0; q < NB / 2; q++)
            *(float4*)(hw + 2 * q) =
                make_float4(hn[2 * q], hn[2 * q], hn[2 * q + 1], hn[2 * q + 1]);

        __syncthreads();
        cur ^= 1;
    }
}

// ---------------------------------------------------------------------------
extern "C" void kernel_launch(void* const* d_in, const int* in_sizes, int n_in,
                              void* d_out, int out_size)
{
    const float* x    = (const float*)d_in[0];
    const float* e1fW = (const float*)d_in[1];
    const float* e1fU = (const float*)d_in[2];
    const float* e1fb = (const float*)d_in[3];
    const float* e1bW = (const float*)d_in[4];
    const float* e1bU = (const float*)d_in[5];
    const float* e1bb = (const float*)d_in[6];
    const float* e2fW = (const float*)d_in[7];
    const float* e2fU = (const float*)d_in[8];
    const float* e2fb = (const float*)d_in[9];
    const float* e2bW = (const float*)d_in[10];
    const float* e2bU = (const float*)d_in[11];
    const float* e2bb = (const float*)d_in[12];
    const float* d1fW = (const float*)d_in[13];
    const float* d1fU = (const float*)d_in[14];
    const float* d1fb = (const float*)d_in[15];
    const float* d1bW = (const float*)d_in[16];
    const float* d1bU = (const float*)d_in[17];
    const float* d1bb = (const float*)d_in[18];
    const float* d2fW = (const float*)d_in[19];
    const float* d2fU = (const float*)d_in[20];
    const float* d2fb = (const float*)d_in[21];
    const float* d2bW = (const float*)d_in[22];
    const float* d2bU = (const float*)d_in[23];
    const float* d2bb = (const float*)d_in[24];
    const float* Wd   = (const float*)d_in[25];
    const float* bd   = (const float*)d_in[26];

    float *xz1, *xz2, *h1, *hd1, *z, *xzd1;
    cudaGetSymbolAddress((void**)&xz1,  g_xz1);
    cudaGetSymbolAddress((void**)&xz2,  g_xz2);
    cudaGetSymbolAddress((void**)&h1,   g_h1);
    cudaGetSymbolAddress((void**)&hd1,  g_hd1);
    cudaGetSymbolAddress((void**)&z,    g_z);
    cudaGetSymbolAddress((void**)&xzd1, g_xzd1);

    const int SMEM128 = 100 * 128 * 16 + 2 * 128 * 8 * 8;
    const int SMEM64  =  64 *  64 * 16 + 2 *  64 * 8 * 8;
    cudaFuncSetAttribute(lstm_kernel<128, 100, true>,
                         cudaFuncAttributeMaxDynamicSharedMemorySize, SMEM128);
    cudaFuncSetAttribute(lstm_kernel<64, 64, true>,
                         cudaFuncAttributeMaxDynamicSharedMemorySize, SMEM64);
    cudaFuncSetAttribute(lstm_kernel<64, 64, false>,
                         cudaFuncAttributeMaxDynamicSharedMemorySize, SMEM64);

    const int T = 256;

    // e1: xz = x @ W + b   (K=64, N=512)
    hmma_gemm<128, 2, 4><<<dim3(4, 1024), 256>>>(x, e1fW, e1fb, xz1,       64, 512, 1024);
    hmma_gemm<128, 2, 4><<<dim3(4, 1024), 256>>>(x, e1bW, e1bb, xz1 + 512, 64, 512, 1024);
    lstm_kernel<128, 100, true><<<dim3(64, 2), 128, SMEM128>>>(
        xz1, (size_t)T * 1024, 1024, e1fU, e1bU, h1, 256, T);

    // e2 (K=256, N=256)
    hmma_gemm<128, 2, 4><<<dim3(2, 1024), 256>>>(h1, e2fW, e2fb, xz2,       256, 256, 512);
    hmma_gemm<128, 2, 4><<<dim3(2, 1024), 256>>>(h1, e2bW, e2bb, xz2 + 256, 256, 256, 512);
    lstm_kernel<64, 64, false><<<dim3(64, 2), 128, SMEM64>>>(
        xz2, (size_t)T * 512, 512, e2fU, e2bU, z, 128, T);

    // d1 (z broadcast over T -> xz once per batch row; M=512, K=128, N=256)
    hmma_gemm<128, 2, 4><<<dim3(2, 4), 256>>>(z, d1fW, d1fb, xzd1,       128, 256, 512);
    hmma_gemm<128, 2, 4><<<dim3(2, 4), 256>>>(z, d1bW, d1bb, xzd1 + 256, 128, 256, 512);
    lstm_kernel<64, 64, true><<<dim3(64, 2), 128, SMEM64>>>(
        xzd1, 512, 0, d1fU, d1bU, hd1, 128, T);

    // d2 (K=128, N=512)
    hmma_gemm<128, 2, 4><<<dim3(4, 1024), 256>>>(hd1, d2fW, d2fb, xz1,       128, 512, 1024);
    hmma_gemm<128, 2, 4><<<dim3(4, 1024), 256>>>(hd1, d2bW, d2bb, xz1 + 512, 128, 512, 1024);
    lstm_kernel<128, 100, true><<<dim3(64, 2), 128, SMEM128>>>(
        xz1, (size_t)T * 1024, 1024, d2fU, d2bU, h1, 256, T);

    // dense (K=256, N=64)
    hmma_gemm<64, 4, 2><<<dim3(1, 1024), 256>>>(h1, Wd, bd, (float*)d_out, 256, 64, 64);
}

// round 8
// speedup vs baseline: 1.9644x; 1.1710x over previous
#include <cuda_runtime.h>
#include <cuda_bf16.h>
#include <cuda_fp16.h>
#include <math.h>
#include <stdint.h>

#define BT 131072
typedef unsigned long long u64;
typedef unsigned int u32;

__device__ float g_xz1[134217728];
__device__ float g_xz2[67108864];
__device__ float g_h1 [33554432];
__device__ float g_hd1[16777216];
__device__ float g_z  [65536];
__device__ float g_xzd1[262144];

__device__ __forceinline__ float sigm(float x) {
    return __fdividef(1.0f, 1.0f + __expf(-x));
}
__device__ __forceinline__ u32 smem_u32(const void* p) {
    u32 a; asm("{ .reg .u64 t; cvta.to.shared.u64 t, %1; cvt.u32.u64 %0, t; }"
               : "=r"(a) : "l"(p));
    return a;
}
__device__ __forceinline__ u32 pkbf(float a, float b) {
    __nv_bfloat162 t = __floats2bfloat162_rn(a, b);
    return *reinterpret_cast<u32*>(&t);
}
__device__ __forceinline__ u32 pkh2(float a, float b) {
    __half2 h = __floats2half2_rn(a, b);
    return *reinterpret_cast<u32*>(&h);
}
__device__ __forceinline__ u64 pkh64(float a, float b, float c, float d) {
    return (u64)pkh2(a, b) | ((u64)pkh2(c, d) << 32);
}
__device__ __forceinline__ float hres(float x) {
    return x - __half2float(__float2half_rn(x));
}
__device__ __forceinline__ void ldsm4(u32 &r0, u32 &r1, u32 &r2, u32 &r3, u32 a) {
    asm volatile("ldmatrix.sync.aligned.m8n8.x4.shared.b16 {%0,%1,%2,%3}, [%4];"
                 : "=r"(r0), "=r"(r1), "=r"(r2), "=r"(r3) : "r"(a));
}
__device__ __forceinline__ void ldsm4t(u32 &r0, u32 &r1, u32 &r2, u32 &r3, u32 a) {
    asm volatile("ldmatrix.sync.aligned.m8n8.x4.trans.shared.b16 {%0,%1,%2,%3}, [%4];"
                 : "=r"(r0), "=r"(r1), "=r"(r2), "=r"(r3) : "r"(a));
}
__device__ __forceinline__ void mma_bf16(float* c, const u32* a, const u32* b) {
    asm volatile("mma.sync.aligned.m16n8k16.row.col.f32.bf16.bf16.f32 "
                 "{%0,%1,%2,%3}, {%4,%5,%6,%7}, {%8,%9}, {%0,%1,%2,%3};"
                 : "+f"(c[0]), "+f"(c[1]), "+f"(c[2]), "+f"(c[3])
                 : "r"(a[0]), "r"(a[1]), "r"(a[2]), "r"(a[3]), "r"(b[0]), "r"(b[1]));
}
__device__ __forceinline__ void mma_f16(float* c, const u32* a, u32 b0, u32 b1) {
    asm volatile("mma.sync.aligned.m16n8k16.row.col.f32.f16.f16.f32 "
                 "{%0,%1,%2,%3}, {%4,%5,%6,%7}, {%8,%9}, {%0,%1,%2,%3};"
                 : "+f"(c[0]), "+f"(c[1]), "+f"(c[2]), "+f"(c[3])
                 : "r"(a[0]), "r"(a[1]), "r"(a[2]), "r"(a[3]), "r"(b0), "r"(b1));
}

// ---------------------------------------------------------------------------
// Split-precision bf16 HMMA GEMM (R6, proven). C = A@W + bias.
// ---------------------------------------------------------------------------
template<int NT, int WM, int WN>
__global__ __launch_bounds__(256, 2)
void hmma_gemm(const float* __restrict__ A, const float* __restrict__ W,
               const float* __restrict__ bias, float* __restrict__ C,
               int K, int Nw, int ldc)
{
    constexpr int PA = 144, PB = NT * 2 + 16;
    constexpr int MW = 128 / WM, NWT = NT / WN;
    constexpr int MFRAG = MW / 16, NFRAG = NWT / 8, BV = NT / 8;

    __shared__ char smA[128 * PA];
    __shared__ char smB[64 * PB];

    const int tid = threadIdx.x, wid = tid >> 5, lane = tid & 31;
    const int bm = blockIdx.y * 128, bn = blockIdx.x * NT;
    const int wm = (wid / WN) * MW, wn = (wid % WN) * NWT;
    const u32 sA = smem_u32(smA), sB = smem_u32(smB);

    float acc[MFRAG][NFRAG][4];
    #pragma unroll
    for (int i = 0; i < MFRAG; i++)
        #pragma unroll
        for (int j = 0; j < NFRAG; j++)
            #pragma unroll
            for (int q = 0; q < 4; q++) acc[i][j][q] = 0.f;

    const int arow = tid >> 1, akq = (tid & 1) * 16;
    const int bkk = tid >> 3, bn0 = (tid & 7) * BV;

    float av[16], bv[BV];
    {
        const float* ap = A + (size_t)(bm + arow) * K + akq;
        #pragma unroll
        for (int i = 0; i < 16; i += 4) *(float4*)(av + i) = *(const float4*)(ap + i);
        const float* bp = W + (size_t)bkk * Nw + bn + bn0;
        #pragma unroll
        for (int i = 0; i < BV; i += 4) *(float4*)(bv + i) = *(const float4*)(bp + i);
    }

    const int nch = K / 32;
    for (int ch = 0; ch < nch; ch++) {
        {
            char* arp = smA + arow * PA;
            #pragma unroll
            for (int i = 0; i < 16; i += 2) {
                float x0 = av[i], x1 = av[i + 1];
                float h0 = __bfloat162float(__float2bfloat16_rn(x0));
                float h1 = __bfloat162float(__float2bfloat16_rn(x1));
                *(u32*)(arp + 2 * (akq + i))      = pkbf(h0, h1);
                *(u32*)(arp + 64 + 2 * (akq + i)) = pkbf(x0 - h0, x1 - h1);
            }
            char* bhi = smB + bkk * PB;
            char* blo = smB + (bkk + 32) * PB;
            #pragma unroll
            for (int i = 0; i < BV; i += 2) {
                float x0 = bv[i], x1 = bv[i + 1];
                float h0 = __bfloat162float(__float2bfloat16_rn(x0));
                float h1 = __bfloat162float(__float2bfloat16_rn(x1));
                *(u32*)(bhi + 2 * (bn0 + i)) = pkbf(h0, h1);
                *(u32*)(blo + 2 * (bn0 + i)) = pkbf(x0 - h0, x1 - h1);
            }
        }
        __syncthreads();
        if (ch + 1 < nch) {
            const int k0 = (ch + 1) * 32;
            const float* ap = A + (size_t)(bm + arow) * K + k0 + akq;
            #pragma unroll
            for (int i = 0; i < 16; i += 4) *(float4*)(av + i) = *(const float4*)(ap + i);
            const float* bp = W + (size_t)(k0 + bkk) * Nw + bn + bn0;
            #pragma unroll
            for (int i = 0; i < BV; i += 4) *(float4*)(bv + i) = *(const float4*)(bp + i);
        }
        #pragma unroll
        for (int term = 0; term < 3; term++) {
            const int aB = (term == 2) ? 1 : 0;
            const int bB = (term == 1) ? 1 : 0;
            #pragma unroll
            for (int s = 0; s < 2; s++) {
                const u32 kbA = (u32)(aB * 32 + s * 16) * 2;
                const int krB = bB * 32 + s * 16;
                u32 a[MFRAG][4];
                #pragma unroll
                for (int mf = 0; mf < MFRAG; mf++)
                    ldsm4(a[mf][0], a[mf][1], a[mf][2], a[mf][3],
                          sA + (u32)(wm + mf * 16 + (lane & 15)) * PA
                             + kbA + ((lane >> 4) << 4));
                u32 b[NFRAG][2];
                #pragma unroll
                for (int np = 0; np < NFRAG / 2; np++) {
                    u32 r0, r1, r2, r3;
                    ldsm4t(r0, r1, r2, r3,
                           sB + (u32)(krB + (lane & 15)) * PB
                              + 2 * (u32)(wn + np * 16 + ((lane >> 4) << 3)));
                    b[2 * np][0] = r0; b[2 * np][1] = r1;
                    b[2 * np + 1][0] = r2; b[2 * np + 1][1] = r3;
                }
                #pragma unroll
                for (int mf = 0; mf < MFRAG; mf++)
                    #pragma unroll
                    for (int nf = 0; nf < NFRAG; nf++)
                        mma_bf16(acc[mf][nf], a[mf], b[nf]);
            }
        }
        __syncthreads();
    }
    #pragma unroll
    for (int mf = 0; mf < MFRAG; mf++) {
        #pragma unroll
        for (int nf = 0; nf < NFRAG; nf++) {
            const int r0 = bm + wm + mf * 16 + (lane >> 2);
            const int cc = bn + wn + nf * 8 + (lane & 3) * 2;
            const float b0 = bias[cc], b1 = bias[cc + 1];
            *(float2*)&C[(size_t)r0 * ldc + cc] =
                make_float2(acc[mf][nf][0] + b0, acc[mf][nf][1] + b1);
            *(float2*)&C[(size_t)(r0 + 8) * ldc + cc] =
                make_float2(acc[mf][nf][2] + b0, acc[mf][nf][3] + b1);
        }
    }
}

// ---------------------------------------------------------------------------
// Tensor-core LSTM recurrence. 256 thr, grid (32 chunks, 2 dirs), 16 rows/CTA.
// U in smem as fragment-linear f16: hi for all K, lo for first KLO k16-blocks.
// h split f16 hi+lo in padded smem. Per step: acc = h_hi@U_hi + h_lo@U_hi
// (+ h_hi@U_lo on KLO blocks); z = acc + xz (fp32, LDG); gates via warp-uniform
// nonlinearity (gate = wid/2); combine through fp32 smem gate buffer.
// ---------------------------------------------------------------------------
template<int HU, int KLO, bool SEQ>
__global__ __launch_bounds__(256, 1)
void lstm_tc(const float* __restrict__ xz, size_t strideB, size_t strideT,
             const float* __restrict__ Uf, const float* __restrict__ Ub,
             float* __restrict__ out, int ldo, int T)
{
    constexpr int NG = 4 * HU, NW = NG / 8, NFRAG = NW / 8;
    constexpr int KF = HU / 16, NFG = NG / 8;
    constexpr int HP = HU + 8;        // h buffer pitch (halves)
    constexpr int GP = NG + 4;        // gate buffer pitch (floats)
    constexpr int NC = HU / 16;       // j's per updater thread

    extern __shared__ char sm[];
    u64*    Uhi  = (u64*)sm;                        // [KF*NFG*32]
    u64*    Ulo  = Uhi + KF * NFG * 32;             // [KLO*NFG*32]
    __half* hhi  = (__half*)(Ulo + KLO * NFG * 32); // [16*HP]
    __half* hlo  = hhi + 16 * HP;
    float*  gbuf = (float*)(hlo + 16 * HP);         // [16*GP]

    const int tid = threadIdx.x, wid = tid >> 5, lane = tid & 31;
    const int g = lane >> 2, c2 = (lane & 3) * 2;
    const int dir = blockIdx.y, b0 = blockIdx.x * 16;
    const float* U   = dir ? Ub : Uf;
    const float* xzd = xz + (size_t)dir * NG;
    float*      outd = out + dir * HU;

    // U -> fragment-linear f16 hi/lo
    for (int idx = tid; idx < KF * NFG * 32; idx += 256) {
        int ln = idx & 31, fr = idx >> 5;
        int nfg = fr % NFG, kf = fr / NFG;
        int n = nfg * 8 + (ln >> 2);
        int k0 = kf * 16 + 2 * (ln & 3);
        float x0 = U[(size_t)k0 * NG + n],       x1 = U[(size_t)(k0 + 1) * NG + n];
        float x2 = U[(size_t)(k0 + 8) * NG + n], x3 = U[(size_t)(k0 + 9) * NG + n];
        Uhi[idx] = pkh64(__half2float(__float2half_rn(x0)),
                         __half2float(__float2half_rn(x1)),
                         __half2float(__float2half_rn(x2)),
                         __half2float(__float2half_rn(x3)));
        if (kf < KLO)
            Ulo[(size_t)(kf * NFG + nfg) * 32 + ln] =
                pkh64(hres(x0), hres(x1), hres(x2), hres(x3));
    }
    for (int idx = tid; idx < 16 * HP / 2; idx += 256) {
        ((u32*)hhi)[idx] = 0; ((u32*)hlo)[idx] = 0;
    }
    __syncthreads();

    const int gate = wid >> 1;
    const int ur = tid >> 4, uj = (tid & 15) * NC;
    float cst[NC];
    #pragma unroll
    for (int i = 0; i < NC; i++) cst[i] = 0.f;

    for (int t = 0; t < T; t++) {
        const int tt = dir ? (T - 1 - t) : t;

        float xv[NFRAG][4];
        {
            const float* xp0 = xzd + (size_t)(b0 + g) * strideB
                               + (size_t)tt * strideT + wid * NW + c2;
            const float* xp1 = xp0 + 8 * strideB;
            #pragma unroll
            for (int nf = 0; nf < NFRAG; nf++) {
                float2 v0 = *(const float2*)(xp0 + nf * 8);
                float2 v1 = *(const float2*)(xp1 + nf * 8);
                xv[nf][0] = v0.x; xv[nf][1] = v0.y;
                xv[nf][2] = v1.x; xv[nf][3] = v1.y;
            }
        }

        float acc[NFRAG][4];
        #pragma unroll
        for (int nf = 0; nf < NFRAG; nf++)
            #pragma unroll
            for (int q = 0; q < 4; q++) acc[nf][q] = 0.f;

        #pragma unroll
        for (int kf = 0; kf < KF; kf++) {
            const int kb = kf * 16 + c2;
            u32 a[4], al[4];
            a[0]  = *(u32*)&hhi[g * HP + kb];       a[1]  = *(u32*)&hhi[(g + 8) * HP + kb];
            a[2]  = *(u32*)&hhi[g * HP + kb + 8];   a[3]  = *(u32*)&hhi[(g + 8) * HP + kb + 8];
            al[0] = *(u32*)&hlo[g * HP + kb];       al[1] = *(u32*)&hlo[(g + 8) * HP + kb];
            al[2] = *(u32*)&hlo[g * HP + kb + 8];   al[3] = *(u32*)&hlo[(g + 8) * HP + kb + 8];
            const u64* ub = Uhi + ((size_t)kf * NFG + wid * NFRAG) * 32 + lane;
            #pragma unroll
            for (int nf = 0; nf < NFRAG; nf++) {
                u64 b = ub[nf * 32];
                mma_f16(acc[nf], a,  (u32)b, (u32)(b >> 32));
                mma_f16(acc[nf], al, (u32)b, (u32)(b >> 32));
            }
            if (kf < KLO) {
                const u64* lb = Ulo + ((size_t)kf * NFG + wid * NFRAG) * 32 + lane;
                #pragma unroll
                for (int nf = 0; nf < NFRAG; nf++) {
                    u64 b = lb[nf * 32];
                    mma_f16(acc[nf], a, (u32)b, (u32)(b >> 32));
                }
            }
        }

        // activate (warp-uniform gate) -> gate buffer
        #pragma unroll
        for (int nf = 0; nf < NFRAG; nf++) {
            const int n = wid * NW + nf * 8 + c2;
            float z0 = acc[nf][0] + xv[nf][0], z1 = acc[nf][1] + xv[nf][1];
            float z2 = acc[nf][2] + xv[nf][2], z3 = acc[nf][3] + xv[nf][3];
            float2 w0, w1;
            if (gate == 2) {
                w0 = make_float2(fmaxf(z0, 0.f), fmaxf(z1, 0.f));
                w1 = make_float2(fmaxf(z2, 0.f), fmaxf(z3, 0.f));
            } else {
                w0 = make_float2(sigm(z0), sigm(z1));
                w1 = make_float2(sigm(z2), sigm(z3));
            }
            *(float2*)&gbuf[g * GP + n]       = w0;
            *(float2*)&gbuf[(g + 8) * GP + n] = w1;
        }
        __syncthreads();

        // update c/h (thread owns row ur, cols uj..uj+NC-1; c in regs)
        {
            float iv[NC], fv[NC], gv[NC], ov[NC], ho[NC];
            const float* gb = gbuf + ur * GP + uj;
            #pragma unroll
            for (int q = 0; q < NC; q += 4) {
                *(float4*)&iv[q] = *(const float4*)(gb + q);
                *(float4*)&fv[q] = *(const float4*)(gb + HU + q);
                *(float4*)&gv[q] = *(const float4*)(gb + 2 * HU + q);
                *(float4*)&ov[q] = *(const float4*)(gb + 3 * HU + q);
            }
            #pragma unroll
            for (int i = 0; i < NC; i++) {
                cst[i] = fv[i] * cst[i] + iv[i] * gv[i];
                ho[i] = ov[i] * fmaxf(cst[i], 0.f);
            }
            if (SEQ) {
                float* op = outd + ((size_t)(b0 + ur) * T + tt) * ldo + uj;
                #pragma unroll
                for (int q = 0; q < NC; q += 4)
                    *(float4*)(op + q) = make_float4(ho[q], ho[q+1], ho[q+2], ho[q+3]);
            } else if (t == T - 1) {
                float* op = outd + (size_t)(b0 + ur) * ldo + uj;
                #pragma unroll
                for (int q = 0; q < NC; q += 4)
                    *(float4*)(op + q) = make_float4(ho[q], ho[q+1], ho[q+2], ho[q+3]);
            }
            u32 hw[NC / 2], lw[NC / 2];
            #pragma unroll
            for (int q = 0; q < NC / 2; q++) {
                float a0 = ho[2 * q], a1 = ho[2 * q + 1];
                float p0 = __half2float(__float2half_rn(a0));
                float p1 = __half2float(__float2half_rn(a1));
                hw[q] = pkh2(p0, p1);
                lw[q] = pkh2(a0 - p0, a1 - p1);
            }
            u32* hp = (u32*)&hhi[ur * HP + uj];
            u32* lp = (u32*)&hlo[ur * HP + uj];
            if constexpr (NC == 8) {
                *(uint4*)hp = make_uint4(hw[0], hw[1], hw[2], hw[3]);
                *(uint4*)lp = make_uint4(lw[0], lw[1], lw[2], lw[3]);
            } else {
                *(uint2*)hp = make_uint2(hw[0], hw[1]);
                *(uint2*)lp = make_uint2(lw[0], lw[1]);
            }
        }
        __syncthreads();
    }
}

// ---------------------------------------------------------------------------
extern "C" void kernel_launch(void* const* d_in, const int* in_sizes, int n_in,
                              void* d_out, int out_size)
{
    const float* x    = (const float*)d_in[0];
    const float* e1fW = (const float*)d_in[1];
    const float* e1fU = (const float*)d_in[2];
    const float* e1fb = (const float*)d_in[3];
    const float* e1bW = (const float*)d_in[4];
    const float* e1bU = (const float*)d_in[5];
    const float* e1bb = (const float*)d_in[6];
    const float* e2fW = (const float*)d_in[7];
    const float* e2fU = (const float*)d_in[8];
    const float* e2fb = (const float*)d_in[9];
    const float* e2bW = (const float*)d_in[10];
    const float* e2bU = (const float*)d_in[11];
    const float* e2bb = (const float*)d_in[12];
    const float* d1fW = (const float*)d_in[13];
    const float* d1fU = (const float*)d_in[14];
    const float* d1fb = (const float*)d_in[15];
    const float* d1bW = (const float*)d_in[16];
    const float* d1bU = (const float*)d_in[17];
    const float* d1bb = (const float*)d_in[18];
    const float* d2fW = (const float*)d_in[19];
    const float* d2fU = (const float*)d_in[20];
    const float* d2fb = (const float*)d_in[21];
    const float* d2bW = (const float*)d_in[22];
    const float* d2bU = (const float*)d_in[23];
    const float* d2bb = (const float*)d_in[24];
    const float* Wd   = (const float*)d_in[25];
    const float* bd   = (const float*)d_in[26];

    float *xz1, *xz2, *h1, *hd1, *z, *xzd1;
    cudaGetSymbolAddress((void**)&xz1,  g_xz1);
    cudaGetSymbolAddress((void**)&xz2,  g_xz2);
    cudaGetSymbolAddress((void**)&h1,   g_h1);
    cudaGetSymbolAddress((void**)&hd1,  g_hd1);
    cudaGetSymbolAddress((void**)&z,    g_z);
    cudaGetSymbolAddress((void**)&xzd1, g_xzd1);

    // lstm_tc smem: HU=128,KLO=3: 131072+49152+8704+33024 = 221952
    //              HU=64, KLO=4:  32768+32768+4608+16640  =  86784
    const int LS128 = 221952, LS64 = 86784;
    cudaFuncSetAttribute(lstm_tc<128, 3, true>,
                         cudaFuncAttributeMaxDynamicSharedMemorySize, LS128);
    cudaFuncSetAttribute(lstm_tc<64, 4, false>,
                         cudaFuncAttributeMaxDynamicSharedMemorySize, LS64);
    cudaFuncSetAttribute(lstm_tc<64, 4, true>,
                         cudaFuncAttributeMaxDynamicSharedMemorySize, LS64);

    const int T = 256;

    // e1 (K=64, N=512)
    hmma_gemm<128, 2, 4><<<dim3(4, 1024), 256>>>(x, e1fW, e1fb, xz1,       64, 512, 1024);
    hmma_gemm<128, 2, 4><<<dim3(4, 1024), 256>>>(x, e1bW, e1bb, xz1 + 512, 64, 512, 1024);
    lstm_tc<128, 3, true><<<dim3(32, 2), 256, LS128>>>(
        xz1, (size_t)T * 1024, 1024, e1fU, e1bU, h1, 256, T);

    // e2 (K=256, N=256)
    hmma_gemm<128, 2, 4><<<dim3(2, 1024), 256>>>(h1, e2fW, e2fb, xz2,       256, 256, 512);
    hmma_gemm<128, 2, 4><<<dim3(2, 1024), 256>>>(h1, e2bW, e2bb, xz2 + 256, 256, 256, 512);
    lstm_tc<64, 4, false><<<dim3(32, 2), 256, LS64>>>(
        xz2, (size_t)T * 512, 512, e2fU, e2bU, z, 128, T);

    // d1 (z broadcast -> xz once per row; M=512, K=128, N=256)
    hmma_gemm<128, 2, 4><<<dim3(2, 4), 256>>>(z, d1fW, d1fb, xzd1,       128, 256, 512);
    hmma_gemm<128, 2, 4><<<dim3(2, 4), 256>>>(z, d1bW, d1bb, xzd1 + 256, 128, 256, 512);
    lstm_tc<64, 4, true><<<dim3(32, 2), 256, LS64>>>(
        xzd1, 512, 0, d1fU, d1bU, hd1, 128, T);

    // d2 (K=128, N=512)
    hmma_gemm<128, 2, 4><<<dim3(4, 1024), 256>>>(hd1, d2fW, d2fb, xz1,       128, 512, 1024);
    hmma_gemm<128, 2, 4><<<dim3(4, 1024), 256>>>(hd1, d2bW, d2bb, xz1 + 512, 128, 512, 1024);
    lstm_tc<128, 3, true><<<dim3(32, 2), 256, LS128>>>(
        xz1, (size_t)T * 1024, 1024, d2fU, d2bU, h1, 256, T);

    // dense (K=256, N=64)
    hmma_gemm<64, 4, 2><<<dim3(1, 1024), 256>>>(h1, Wd, bd, (float*)d_out, 256, 64, 64);
}

// round 9
// speedup vs baseline: 2.0216x; 1.0291x over previous
#include <cuda_runtime.h>
#include <cuda_bf16.h>
#include <cuda_fp16.h>
#include <math.h>
#include <stdint.h>

#define BT 131072
typedef unsigned long long u64;
typedef unsigned int u32;

__device__ float g_xz1[134217728];
__device__ float g_xz2[67108864];
__device__ float g_h1 [33554432];
__device__ float g_hd1[16777216];
__device__ float g_z  [65536];
__device__ float g_xzd1[262144];

__device__ __forceinline__ float sigm(float x) {
    return __fdividef(1.0f, 1.0f + __expf(-x));
}
__device__ __forceinline__ u32 smem_u32(const void* p) {
    u32 a; asm("{ .reg .u64 t; cvta.to.shared.u64 t, %1; cvt.u32.u64 %0, t; }"
               : "=r"(a) : "l"(p));
    return a;
}
__device__ __forceinline__ u32 pkbf(float a, float b) {
    __nv_bfloat162 t = __floats2bfloat162_rn(a, b);
    return *reinterpret_cast<u32*>(&t);
}
__device__ __forceinline__ u32 pkh2(float a, float b) {
    __half2 h = __floats2half2_rn(a, b);
    return *reinterpret_cast<u32*>(&h);
}
__device__ __forceinline__ u64 pkh64(float a, float b, float c, float d) {
    return (u64)pkh2(a, b) | ((u64)pkh2(c, d) << 32);
}
__device__ __forceinline__ float hres(float x) {
    return x - __half2float(__float2half_rn(x));
}
__device__ __forceinline__ void ldsm4(u32 &r0, u32 &r1, u32 &r2, u32 &r3, u32 a) {
    asm volatile("ldmatrix.sync.aligned.m8n8.x4.shared.b16 {%0,%1,%2,%3}, [%4];"
                 : "=r"(r0), "=r"(r1), "=r"(r2), "=r"(r3) : "r"(a));
}
__device__ __forceinline__ void ldsm4t(u32 &r0, u32 &r1, u32 &r2, u32 &r3, u32 a) {
    asm volatile("ldmatrix.sync.aligned.m8n8.x4.trans.shared.b16 {%0,%1,%2,%3}, [%4];"
                 : "=r"(r0), "=r"(r1), "=r"(r2), "=r"(r3) : "r"(a));
}
__device__ __forceinline__ void mma_bf16(float* c, const u32* a, const u32* b) {
    asm volatile("mma.sync.aligned.m16n8k16.row.col.f32.bf16.bf16.f32 "
                 "{%0,%1,%2,%3}, {%4,%5,%6,%7}, {%8,%9}, {%0,%1,%2,%3};"
                 : "+f"(c[0]), "+f"(c[1]), "+f"(c[2]), "+f"(c[3])
                 : "r"(a[0]), "r"(a[1]), "r"(a[2]), "r"(a[3]), "r"(b[0]), "r"(b[1]));
}
__device__ __forceinline__ void mma_f16(float* c, const u32* a, u32 b0, u32 b1) {
    asm volatile("mma.sync.aligned.m16n8k16.row.col.f32.f16.f16.f32 "
                 "{%0,%1,%2,%3}, {%4,%5,%6,%7}, {%8,%9}, {%0,%1,%2,%3};"
                 : "+f"(c[0]), "+f"(c[1]), "+f"(c[2]), "+f"(c[3])
                 : "r"(a[0]), "r"(a[1]), "r"(a[2]), "r"(a[3]), "r"(b0), "r"(b1));
}

// ---------------------------------------------------------------------------
// Split-precision bf16 HMMA GEMM (proven). C = A@W + bias.
// ---------------------------------------------------------------------------
template<int NT, int WM, int WN>
__global__ __launch_bounds__(256, 2)
void hmma_gemm(const float* __restrict__ A, const float* __restrict__ W,
               const float* __restrict__ bias, float* __restrict__ C,
               int K, int Nw, int ldc)
{
    constexpr int PA = 144, PB = NT * 2 + 16;
    constexpr int MW = 128 / WM, NWT = NT / WN;
    constexpr int MFRAG = MW / 16, NFRAG = NWT / 8, BV = NT / 8;

    __shared__ char smA[128 * PA];
    __shared__ char smB[64 * PB];

    const int tid = threadIdx.x, wid = tid >> 5, lane = tid & 31;
    const int bm = blockIdx.y * 128, bn = blockIdx.x * NT;
    const int wm = (wid / WN) * MW, wn = (wid % WN) * NWT;
    const u32 sA = smem_u32(smA), sB = smem_u32(smB);

    float acc[MFRAG][NFRAG][4];
    #pragma unroll
    for (int i = 0; i < MFRAG; i++)
        #pragma unroll
        for (int j = 0; j < NFRAG; j++)
            #pragma unroll
            for (int q = 0; q < 4; q++) acc[i][j][q] = 0.f;

    const int arow = tid >> 1, akq = (tid & 1) * 16;
    const int bkk = tid >> 3, bn0 = (tid & 7) * BV;

    float av[16], bv[BV];
    {
        const float* ap = A + (size_t)(bm + arow) * K + akq;
        #pragma unroll
        for (int i = 0; i < 16; i += 4) *(float4*)(av + i) = *(const float4*)(ap + i);
        const float* bp = W + (size_t)bkk * Nw + bn + bn0;
        #pragma unroll
        for (int i = 0; i < BV; i += 4) *(float4*)(bv + i) = *(const float4*)(bp + i);
    }

    const int nch = K / 32;
    for (int ch = 0; ch < nch; ch++) {
        {
            char* arp = smA + arow * PA;
            #pragma unroll
            for (int i = 0; i < 16; i += 2) {
                float x0 = av[i], x1 = av[i + 1];
                float h0 = __bfloat162float(__float2bfloat16_rn(x0));
                float h1 = __bfloat162float(__float2bfloat16_rn(x1));
                *(u32*)(arp + 2 * (akq + i))      = pkbf(h0, h1);
                *(u32*)(arp + 64 + 2 * (akq + i)) = pkbf(x0 - h0, x1 - h1);
            }
            char* bhi = smB + bkk * PB;
            char* blo = smB + (bkk + 32) * PB;
            #pragma unroll
            for (int i = 0; i < BV; i += 2) {
                float x0 = bv[i], x1 = bv[i + 1];
                float h0 = __bfloat162float(__float2bfloat16_rn(x0));
                float h1 = __bfloat162float(__float2bfloat16_rn(x1));
                *(u32*)(bhi + 2 * (bn0 + i)) = pkbf(h0, h1);
                *(u32*)(blo + 2 * (bn0 + i)) = pkbf(x0 - h0, x1 - h1);
            }
        }
        __syncthreads();
        if (ch + 1 < nch) {
            const int k0 = (ch + 1) * 32;
            const float* ap = A + (size_t)(bm + arow) * K + k0 + akq;
            #pragma unroll
            for (int i = 0; i < 16; i += 4) *(float4*)(av + i) = *(const float4*)(ap + i);
            const float* bp = W + (size_t)(k0 + bkk) * Nw + bn + bn0;
            #pragma unroll
            for (int i = 0; i < BV; i += 4) *(float4*)(bv + i) = *(const float4*)(bp + i);
        }
        #pragma unroll
        for (int term = 0; term < 3; term++) {
            const int aB = (term == 2) ? 1 : 0;
            const int bB = (term == 1) ? 1 : 0;
            #pragma unroll
            for (int s = 0; s < 2; s++) {
                const u32 kbA = (u32)(aB * 32 + s * 16) * 2;
                const int krB = bB * 32 + s * 16;
                u32 a[MFRAG][4];
                #pragma unroll
                for (int mf = 0; mf < MFRAG; mf++)
                    ldsm4(a[mf][0], a[mf][1], a[mf][2], a[mf][3],
                          sA + (u32)(wm + mf * 16 + (lane & 15)) * PA
                             + kbA + ((lane >> 4) << 4));
                u32 b[NFRAG][2];
                #pragma unroll
                for (int np = 0; np < NFRAG / 2; np++) {
                    u32 r0, r1, r2, r3;
                    ldsm4t(r0, r1, r2, r3,
                           sB + (u32)(krB + (lane & 15)) * PB
                              + 2 * (u32)(wn + np * 16 + ((lane >> 4) << 3)));
                    b[2 * np][0] = r0; b[2 * np][1] = r1;
                    b[2 * np + 1][0] = r2; b[2 * np + 1][1] = r3;
                }
                #pragma unroll
                for (int mf = 0; mf < MFRAG; mf++)
                    #pragma unroll
                    for (int nf = 0; nf < NFRAG; nf++)
                        mma_bf16(acc[mf][nf], a[mf], b[nf]);
            }
        }
        __syncthreads();
    }
    #pragma unroll
    for (int mf = 0; mf < MFRAG; mf++) {
        #pragma unroll
        for (int nf = 0; nf < NFRAG; nf++) {
            const int r0 = bm + wm + mf * 16 + (lane >> 2);
            const int cc = bn + wn + nf * 8 + (lane & 3) * 2;
            const float b0 = bias[cc], b1 = bias[cc + 1];
            *(float2*)&C[(size_t)r0 * ldc + cc] =
                make_float2(acc[mf][nf][0] + b0, acc[mf][nf][1] + b1);
            *(float2*)&C[(size_t)(r0 + 8) * ldc + cc] =
                make_float2(acc[mf][nf][2] + b0, acc[mf][nf][3] + b1);
        }
    }
}

// ---------------------------------------------------------------------------
// Tensor-core LSTM. 512 threads (16 warps = 4/SMSP), grid (32 chunks, 2 dirs),
// 16 batch rows/CTA. Each warp owns NW = NG/16 gate-columns.
// U in smem fragment-linear f16 (hi all K; lo first KLO k16-blocks).
// h split f16 hi+lo. acc = h_hi@U_hi + h_lo@U_hi (+ h_hi@U_lo on KLO blocks).
// ---------------------------------------------------------------------------
template<int HU, int KLO, bool SEQ>
__global__ __launch_bounds__(512, 1)
void lstm_tc(const float* __restrict__ xz, size_t strideB, size_t strideT,
             const float* __restrict__ Uf, const float* __restrict__ Ub,
             float* __restrict__ out, int ldo, int T)
{
    constexpr int NG = 4 * HU, NW = NG / 16, NFRAG = NW / 8;
    constexpr int KF = HU / 16, NFG = NG / 8;
    constexpr int HP = HU + 8;
    constexpr int GP = NG + 4;
    constexpr int NC = HU / 32;       // cols per updater thread (4 or 2)

    extern __shared__ char sm[];
    u64*    Uhi  = (u64*)sm;                        // [KF*NFG*32]
    u64*    Ulo  = Uhi + KF * NFG * 32;             // [KLO*NFG*32]
    __half* hhi  = (__half*)(Ulo + KLO * NFG * 32); // [16*HP]
    __half* hlo  = hhi + 16 * HP;
    float*  gbuf = (float*)(hlo + 16 * HP);         // [16*GP]

    const int tid = threadIdx.x, wid = tid >> 5, lane = tid & 31;
    const int g = lane >> 2, c2 = (lane & 3) * 2;
    const int dir = blockIdx.y, b0 = blockIdx.x * 16;
    const float* U   = dir ? Ub : Uf;
    const float* xzd = xz + (size_t)dir * NG;
    float*      outd = out + dir * HU;

    for (int idx = tid; idx < KF * NFG * 32; idx += 512) {
        int ln = idx & 31, fr = idx >> 5;
        int nfg = fr % NFG, kf = fr / NFG;
        int n = nfg * 8 + (ln >> 2);
        int k0 = kf * 16 + 2 * (ln & 3);
        float x0 = U[(size_t)k0 * NG + n],       x1 = U[(size_t)(k0 + 1) * NG + n];
        float x2 = U[(size_t)(k0 + 8) * NG + n], x3 = U[(size_t)(k0 + 9) * NG + n];
        Uhi[idx] = pkh64(__half2float(__float2half_rn(x0)),
                         __half2float(__float2half_rn(x1)),
                         __half2float(__float2half_rn(x2)),
                         __half2float(__float2half_rn(x3)));
        if (kf < KLO)
            Ulo[(size_t)(kf * NFG + nfg) * 32 + ln] =
                pkh64(hres(x0), hres(x1), hres(x2), hres(x3));
    }
    for (int idx = tid; idx < 16 * HP / 2; idx += 512) {
        ((u32*)hhi)[idx] = 0; ((u32*)hlo)[idx] = 0;
    }
    __syncthreads();

    const int gate = (wid * NW) / HU;        // warp-uniform gate id
    const int ur = tid >> 5, uj = (tid & 31) * NC;
    float cst[NC];
    #pragma unroll
    for (int i = 0; i < NC; i++) cst[i] = 0.f;

    for (int t = 0; t < T; t++) {
        const int tt = dir ? (T - 1 - t) : t;

        float xv[NFRAG][4];
        {
            const float* xp0 = xzd + (size_t)(b0 + g) * strideB
                               + (size_t)tt * strideT + wid * NW + c2;
            const float* xp1 = xp0 + 8 * strideB;
            #pragma unroll
            for (int nf = 0; nf < NFRAG; nf++) {
                float2 v0 = *(const float2*)(xp0 + nf * 8);
                float2 v1 = *(const float2*)(xp1 + nf * 8);
                xv[nf][0] = v0.x; xv[nf][1] = v0.y;
                xv[nf][2] = v1.x; xv[nf][3] = v1.y;
            }
        }

        float acc[NFRAG][4];
        #pragma unroll
        for (int nf = 0; nf < NFRAG; nf++)
            #pragma unroll
            for (int q = 0; q < 4; q++) acc[nf][q] = 0.f;

        #pragma unroll
        for (int kf = 0; kf < KF; kf++) {
            const int kb = kf * 16 + c2;
            u32 a[4], al[4];
            a[0]  = *(u32*)&hhi[g * HP + kb];       a[1]  = *(u32*)&hhi[(g + 8) * HP + kb];
            a[2]  = *(u32*)&hhi[g * HP + kb + 8];   a[3]  = *(u32*)&hhi[(g + 8) * HP + kb + 8];
            al[0] = *(u32*)&hlo[g * HP + kb];       al[1] = *(u32*)&hlo[(g + 8) * HP + kb];
            al[2] = *(u32*)&hlo[g * HP + kb + 8];   al[3] = *(u32*)&hlo[(g + 8) * HP + kb + 8];
            const u64* ub = Uhi + ((size_t)kf * NFG + wid * NFRAG) * 32 + lane;
            #pragma unroll
            for (int nf = 0; nf < NFRAG; nf++) {
                u64 b = ub[nf * 32];
                mma_f16(acc[nf], a,  (u32)b, (u32)(b >> 32));
                mma_f16(acc[nf], al, (u32)b, (u32)(b >> 32));
            }
            if (kf < KLO) {
                const u64* lb = Ulo + ((size_t)kf * NFG + wid * NFRAG) * 32 + lane;
                #pragma unroll
                for (int nf = 0; nf < NFRAG; nf++) {
                    u64 b = lb[nf * 32];
                    mma_f16(acc[nf], a, (u32)b, (u32)(b >> 32));
                }
            }
        }

        #pragma unroll
        for (int nf = 0; nf < NFRAG; nf++) {
            const int n = wid * NW + nf * 8 + c2;
            float z0 = acc[nf][0] + xv[nf][0], z1 = acc[nf][1] + xv[nf][1];
            float z2 = acc[nf][2] + xv[nf][2], z3 = acc[nf][3] + xv[nf][3];
            float2 w0, w1;
            if (gate == 2) {
                w0 = make_float2(fmaxf(z0, 0.f), fmaxf(z1, 0.f));
                w1 = make_float2(fmaxf(z2, 0.f), fmaxf(z3, 0.f));
            } else {
                w0 = make_float2(sigm(z0), sigm(z1));
                w1 = make_float2(sigm(z2), sigm(z3));
            }
            *(float2*)&gbuf[g * GP + n]       = w0;
            *(float2*)&gbuf[(g + 8) * GP + n] = w1;
        }
        __syncthreads();

        {
            float iv[NC], fv[NC], gv[NC], ov[NC], ho[NC];
            const float* gb = gbuf + ur * GP + uj;
            if constexpr (NC == 4) {
                *(float4*)iv = *(const float4*)(gb);
                *(float4*)fv = *(const float4*)(gb + HU);
                *(float4*)gv = *(const float4*)(gb + 2 * HU);
                *(float4*)ov = *(const float4*)(gb + 3 * HU);
            } else {
                *(float2*)iv = *(const float2*)(gb);
                *(float2*)fv = *(const float2*)(gb + HU);
                *(float2*)gv = *(const float2*)(gb + 2 * HU);
                *(float2*)ov = *(const float2*)(gb + 3 * HU);
            }
            #pragma unroll
            for (int i = 0; i < NC; i++) {
                cst[i] = fv[i] * cst[i] + iv[i] * gv[i];
                ho[i] = ov[i] * fmaxf(cst[i], 0.f);
            }
            if (SEQ) {
                float* op = outd + ((size_t)(b0 + ur) * T + tt) * ldo + uj;
                if constexpr (NC == 4)
                    *(float4*)op = make_float4(ho[0], ho[1], ho[2], ho[3]);
                else
                    *(float2*)op = make_float2(ho[0], ho[1]);
            } else if (t == T - 1) {
                float* op = outd + (size_t)(b0 + ur) * ldo + uj;
                if constexpr (NC == 4)
                    *(float4*)op = make_float4(ho[0], ho[1], ho[2], ho[3]);
                else
                    *(float2*)op = make_float2(ho[0], ho[1]);
            }
            u32 hw[NC / 2], lw[NC / 2];
            #pragma unroll
            for (int q = 0; q < NC / 2; q++) {
                float a0 = ho[2 * q], a1 = ho[2 * q + 1];
                float p0 = __half2float(__float2half_rn(a0));
                float p1 = __half2float(__float2half_rn(a1));
                hw[q] = pkh2(p0, p1);
                lw[q] = pkh2(a0 - p0, a1 - p1);
            }
            u32* hp = (u32*)&hhi[ur * HP + uj];
            u32* lp = (u32*)&hlo[ur * HP + uj];
            if constexpr (NC == 4) {
                *(uint2*)hp = make_uint2(hw[0], hw[1]);
                *(uint2*)lp = make_uint2(lw[0], lw[1]);
            } else {
                hp[0] = hw[0]; lp[0] = lw[0];
            }
        }
        __syncthreads();
    }
}

// ---------------------------------------------------------------------------
extern "C" void kernel_launch(void* const* d_in, const int* in_sizes, int n_in,
                              void* d_out, int out_size)
{
    const float* x    = (const float*)d_in[0];
    const float* e1fW = (const float*)d_in[1];
    const float* e1fU = (const float*)d_in[2];
    const float* e1fb = (const float*)d_in[3];
    const float* e1bW = (const float*)d_in[4];
    const float* e1bU = (const float*)d_in[5];
    const float* e1bb = (const float*)d_in[6];
    const float* e2fW = (const float*)d_in[7];
    const float* e2fU = (const float*)d_in[8];
    const float* e2fb = (const float*)d_in[9];
    const float* e2bW = (const float*)d_in[10];
    const float* e2bU = (const float*)d_in[11];
    const float* e2bb = (const float*)d_in[12];
    const float* d1fW = (const float*)d_in[13];
    const float* d1fU = (const float*)d_in[14];
    const float* d1fb = (const float*)d_in[15];
    const float* d1bW = (const float*)d_in[16];
    const float* d1bU = (const float*)d_in[17];
    const float* d1bb = (const float*)d_in[18];
    const float* d2fW = (const float*)d_in[19];
    const float* d2fU = (const float*)d_in[20];
    const float* d2fb = (const float*)d_in[21];
    const float* d2bW = (const float*)d_in[22];
    const float* d2bU = (const float*)d_in[23];
    const float* d2bb = (const float*)d_in[24];
    const float* Wd   = (const float*)d_in[25];
    const float* bd   = (const float*)d_in[26];

    float *xz1, *xz2, *h1, *hd1, *z, *xzd1;
    cudaGetSymbolAddress((void**)&xz1,  g_xz1);
    cudaGetSymbolAddress((void**)&xz2,  g_xz2);
    cudaGetSymbolAddress((void**)&h1,   g_h1);
    cudaGetSymbolAddress((void**)&hd1,  g_hd1);
    cudaGetSymbolAddress((void**)&z,    g_z);
    cudaGetSymbolAddress((void**)&xzd1, g_xzd1);

    // smem: HU=128,KLO=2: 131072+32768+8704+33024 = 205568
    //       HU=64, KLO=4:  32768+32768+4608+16640 =  86784
    const int LS128 = 205568, LS64 = 86784;
    cudaFuncSetAttribute(lstm_tc<128, 2, true>,
                         cudaFuncAttributeMaxDynamicSharedMemorySize, LS128);
    cudaFuncSetAttribute(lstm_tc<64, 4, false>,
                         cudaFuncAttributeMaxDynamicSharedMemorySize, LS64);
    cudaFuncSetAttribute(lstm_tc<64, 4, true>,
                         cudaFuncAttributeMaxDynamicSharedMemorySize, LS64);

    const int T = 256;

    // e1 (K=64, N=512)
    hmma_gemm<128, 2, 4><<<dim3(4, 1024), 256>>>(x, e1fW, e1fb, xz1,       64, 512, 1024);
    hmma_gemm<128, 2, 4><<<dim3(4, 1024), 256>>>(x, e1bW, e1bb, xz1 + 512, 64, 512, 1024);
    lstm_tc<128, 2, true><<<dim3(32, 2), 512, LS128>>>(
        xz1, (size_t)T * 1024, 1024, e1fU, e1bU, h1, 256, T);

    // e2 (K=256, N=256)
    hmma_gemm<128, 2, 4><<<dim3(2, 1024), 256>>>(h1, e2fW, e2fb, xz2,       256, 256, 512);
    hmma_gemm<128, 2, 4><<<dim3(2, 1024), 256>>>(h1, e2bW, e2bb, xz2 + 256, 256, 256, 512);
    lstm_tc<64, 4, false><<<dim3(32, 2), 512, LS64>>>(
        xz2, (size_t)T * 512, 512, e2fU, e2bU, z, 128, T);

    // d1 (z broadcast -> xz once per row; M=512, K=128, N=256)
    hmma_gemm<128, 2, 4><<<dim3(2, 4), 256>>>(z, d1fW, d1fb, xzd1,       128, 256, 512);
    hmma_gemm<128, 2, 4><<<dim3(2, 4), 256>>>(z, d1bW, d1bb, xzd1 + 256, 128, 256, 512);
    lstm_tc<64, 4, true><<<dim3(32, 2), 512, LS64>>>(
        xzd1, 512, 0, d1fU, d1bU, hd1, 128, T);

    // d2 (K=128, N=512)
    hmma_gemm<128, 2, 4><<<dim3(4, 1024), 256>>>(hd1, d2fW, d2fb, xz1,       128, 512, 1024);
    hmma_gemm<128, 2, 4><<<dim3(4, 1024), 256>>>(hd1, d2bW, d2bb, xz1 + 512, 128, 512, 1024);
    lstm_tc<128, 2, true><<<dim3(32, 2), 512, LS128>>>(
        xz1, (size_t)T * 1024, 1024, d2fU, d2bU, h1, 256, T);

    // dense (K=256, N=64)
    hmma_gemm<64, 4, 2><<<dim3(1, 1024), 256>>>(h1, Wd, bd, (float*)d_out, 256, 64, 64);
}

// round 11
// speedup vs baseline: 2.0238x; 1.0011x over previous
#include <cuda_runtime.h>
#include <cuda_bf16.h>
#include <cuda_fp16.h>
#include <math.h>
#include <stdint.h>

#define BT 131072
typedef unsigned long long u64;
typedef unsigned int u32;
typedef __nv_bfloat16 bf16;

// fp32 scratch
__device__ float g_xz1 [134217728];   // [BT,1024]
__device__ float g_xz2 [67108864];    // [BT, 512]
__device__ float g_xzd1[262144];      // [B, 512]
// bf16 hi/lo planes
__device__ bf16 g_xhi  [8388608],  g_xlo  [8388608];    // x   [BT,64]
__device__ bf16 g_h1hi [33554432], g_h1lo [33554432];   // h1  [BT,256]
__device__ bf16 g_hd1hi[16777216], g_hd1lo[16777216];   // hd1 [BT,128]
__device__ bf16 g_zhi  [65536],    g_zlo  [65536];      // z   [B,128]
__device__ bf16 g_whi  [409600],   g_wlo  [409600];     // all weights

__device__ __forceinline__ float sigm(float x) {
    return __fdividef(1.0f, 1.0f + __expf(-x));
}
__device__ __forceinline__ u32 smem_u32(const void* p) {
    u32 a; asm("{ .reg .u64 t; cvta.to.shared.u64 t, %1; cvt.u32.u64 %0, t; }"
               : "=r"(a) : "l"(p));
    return a;
}
__device__ __forceinline__ u32 pkbf(float a, float b) {
    __nv_bfloat162 t = __floats2bfloat162_rn(a, b);
    return *reinterpret_cast<u32*>(&t);
}
__device__ __forceinline__ float bres(float x) {
    return x - __bfloat162float(__float2bfloat16_rn(x));
}
__device__ __forceinline__ u32 pkh2(float a, float b) {
    __half2 h = __floats2half2_rn(a, b);
    return *reinterpret_cast<u32*>(&h);
}
__device__ __forceinline__ u64 pkh64(float a, float b, float c, float d) {
    return (u64)pkh2(a, b) | ((u64)pkh2(c, d) << 32);
}
__device__ __forceinline__ float hres(float x) {
    return x - __half2float(__float2half_rn(x));
}
__device__ __forceinline__ void ldsm4(u32 &r0, u32 &r1, u32 &r2, u32 &r3, u32 a) {
    asm volatile("ldmatrix.sync.aligned.m8n8.x4.shared.b16 {%0,%1,%2,%3}, [%4];"
                 : "=r"(r0), "=r"(r1), "=r"(r2), "=r"(r3) : "r"(a));
}
__device__ __forceinline__ void ldsm4t(u32 &r0, u32 &r1, u32 &r2, u32 &r3, u32 a) {
    asm volatile("ldmatrix.sync.aligned.m8n8.x4.trans.shared.b16 {%0,%1,%2,%3}, [%4];"
                 : "=r"(r0), "=r"(r1), "=r"(r2), "=r"(r3) : "r"(a));
}
__device__ __forceinline__ void mma_bf16(float* c, const u32* a, const u32* b) {
    asm volatile("mma.sync.aligned.m16n8k16.row.col.f32.bf16.bf16.f32 "
                 "{%0,%1,%2,%3}, {%4,%5,%6,%7}, {%8,%9}, {%0,%1,%2,%3};"
                 : "+f"(c[0]), "+f"(c[1]), "+f"(c[2]), "+f"(c[3])
                 : "r"(a[0]), "r"(a[1]), "r"(a[2]), "r"(a[3]), "r"(b[0]), "r"(b[1]));
}
__device__ __forceinline__ void mma_f16(float* c, const u32* a, u32 b0, u32 b1) {
    asm volatile("mma.sync.aligned.m16n8k16.row.col.f32.f16.f16.f32 "
                 "{%0,%1,%2,%3}, {%4,%5,%6,%7}, {%8,%9}, {%0,%1,%2,%3};"
                 : "+f"(c[0]), "+f"(c[1]), "+f"(c[2]), "+f"(c[3])
                 : "r"(a[0]), "r"(a[1]), "r"(a[2]), "r"(a[3]), "r"(b0), "r"(b1));
}
__device__ __forceinline__ void cp8(u32 d, const void* s) {
    asm volatile("cp.async.ca.shared.global [%0], [%1], 8;" :: "r"(d), "l"(s));
}
__device__ __forceinline__ void cp16(u32 d, const void* s) {
    asm volatile("cp.async.ca.shared.global [%0], [%1], 16;" :: "r"(d), "l"(s));
}

// ---------------------------------------------------------------------------
// Convert kernels: fp32 -> bf16 hi/lo planes
// ---------------------------------------------------------------------------
__global__ void cvt_x(const float* __restrict__ s, bf16* __restrict__ hi,
                      bf16* __restrict__ lo, int n4)
{
    for (int i = blockIdx.x * blockDim.x + threadIdx.x; i < n4;
         i += gridDim.x * blockDim.x) {
        float4 v = ((const float4*)s)[i];
        ((uint2*)hi)[i] = make_uint2(pkbf(v.x, v.y), pkbf(v.z, v.w));
        ((uint2*)lo)[i] = make_uint2(pkbf(bres(v.x), bres(v.y)),
                                     pkbf(bres(v.z), bres(v.w)));
    }
}

__global__ void cvt_w9(const float* w0, const float* w1, const float* w2,
                       const float* w3, const float* w4, const float* w5,
                       const float* w6, const float* w7, const float* w8,
                       bf16* __restrict__ hi, bf16* __restrict__ lo)
{
    const int off[10] = {0, 8192, 16384, 32768, 49152, 57344,
                         65536, 81920, 98304, 102400};   // float4 units
    const float* ws[9] = {w0, w1, w2, w3, w4, w5, w6, w7, w8};
    for (int i = blockIdx.x * blockDim.x + threadIdx.x; i < 102400;
         i += gridDim.x * blockDim.x) {
        int s = 0;
        #pragma unroll
        for (int k = 1; k < 9; k++) if (i >= off[k]) s = k;
        float4 v = ((const float4*)ws[s])[i - off[s]];
        ((uint2*)hi)[i] = make_uint2(pkbf(v.x, v.y), pkbf(v.z, v.w));
        ((uint2*)lo)[i] = make_uint2(pkbf(bres(v.x), bres(v.y)),
                                     pkbf(bres(v.z), bres(v.w)));
    }
}

// ---------------------------------------------------------------------------
// hgemm2: C = A@W + bias; A,W pre-split bf16 hi/lo planes; cp.async pipeline.
// PA=80 (multiple of 16 — ldmatrix row alignment requirement).
// ---------------------------------------------------------------------------
template<int NT>
__device__ __forceinline__ void g2s_chunk(
    u32 sbase, const bf16* Ahi, const bf16* Alo,
    const bf16* Whi, const bf16* Wlo,
    int bm, int bn, int k0, int K, int Nw, int tid)
{
    constexpr int PA = 80, ASZ = 128 * PA;
    constexpr int PB = NT * 2 + 16, WSZ = 32 * PB;
    constexpr int WOPS = NT / 32;
    {
        int row = tid & 127;
        const bf16* src = ((tid & 128) ? Alo : Ahi) + (size_t)(bm + row) * K + k0;
        u32 dst = sbase + ((tid & 128) ? ASZ : 0) + row * PA;
        #pragma unroll
        for (int i = 0; i < 8; i++)
            cp8(dst + i * 8, (const char*)src + i * 8);
    }
    {
        int idx = tid & 127, row = idx >> 2, seg = idx & 3;
        const bf16* src = ((tid & 128) ? Wlo : Whi)
                          + (size_t)(k0 + row) * Nw + bn + seg * (NT / 4);
        u32 dst = sbase + 2 * ASZ + ((tid & 128) ? WSZ : 0) + row * PB + seg * (NT / 2);
        #pragma unroll
        for (int i = 0; i < WOPS; i++)
            cp16(dst + i * 16, (const char*)src + i * 16);
    }
}

template<int NT, int WM, int WN>
__global__ __launch_bounds__(256, 2)
void hgemm2(const bf16* __restrict__ Ahi, const bf16* __restrict__ Alo,
            const bf16* __restrict__ Whi0, const bf16* __restrict__ Wlo0,
            const bf16* __restrict__ Whi1, const bf16* __restrict__ Wlo1,
            const float* __restrict__ bias0, const float* __restrict__ bias1,
            float* __restrict__ C, int K, int Nw, int ldc, int coff)
{
    constexpr int PA = 80, ASZ = 128 * PA;
    constexpr int PB = NT * 2 + 16, WSZ = 32 * PB;
    constexpr int STG = 2 * ASZ + 2 * WSZ;
    constexpr int MW = 128 / WM, NWT = NT / WN;
    constexpr int MFRAG = MW / 16, NFRAG = NWT / 8;
    extern __shared__ char gsm[];

    const int tid = threadIdx.x, wid = tid >> 5, lane = tid & 31;
    const int bm = blockIdx.y * 128, bn = blockIdx.x * NT, dir = blockIdx.z;
    const int wm = (wid / WN) * MW, wn = (wid % WN) * NWT;
    const bf16* Whi = dir ? Whi1 : Whi0;
    const bf16* Wlo = dir ? Wlo1 : Wlo0;
    const float* bias = dir ? bias1 : bias0;
    const int cofs = dir * coff;
    const u32 sb = smem_u32(gsm);

    float acc[MFRAG][NFRAG][4];
    #pragma unroll
    for (int i = 0; i < MFRAG; i++)
        #pragma unroll
        for (int j = 0; j < NFRAG; j++)
            #pragma unroll
            for (int q = 0; q < 4; q++) acc[i][j][q] = 0.f;

    g2s_chunk<NT>(sb, Ahi, Alo, Whi, Wlo, bm, bn, 0, K, Nw, tid);
    asm volatile("cp.async.commit_group;" ::: "memory");

    const int nch = K / 32;
    for (int ch = 0; ch < nch; ch++) {
        asm volatile("cp.async.wait_group 0;" ::: "memory");
        __syncthreads();
        const u32 s0 = sb + (u32)(ch & 1) * STG;
        if (ch + 1 < nch) {
            g2s_chunk<NT>(sb + (u32)((ch + 1) & 1) * STG, Ahi, Alo, Whi, Wlo,
                          bm, bn, (ch + 1) * 32, K, Nw, tid);
            asm volatile("cp.async.commit_group;" ::: "memory");
        }
        const u32 saH = s0, saL = s0 + ASZ, swH = s0 + 2 * ASZ, swL = swH + WSZ;
        #pragma unroll
        for (int s = 0; s < 2; s++) {
            u32 wh[NFRAG][2], wl[NFRAG][2];
            #pragma unroll
            for (int np = 0; np < NFRAG / 2; np++) {
                u32 r0, r1, r2, r3;
                const u32 colb = 2 * (u32)(wn + np * 16 + ((lane >> 4) << 3));
                const u32 rowb = (u32)(s * 16 + (lane & 15)) * PB;
                ldsm4t(r0, r1, r2, r3, swH + rowb + colb);
                wh[2*np][0] = r0; wh[2*np][1] = r1;
                wh[2*np+1][0] = r2; wh[2*np+1][1] = r3;
                ldsm4t(r0, r1, r2, r3, swL + rowb + colb);
                wl[2*np][0] = r0; wl[2*np][1] = r1;
                wl[2*np+1][0] = r2; wl[2*np+1][1] = r3;
            }
            u32 a[MFRAG][4];
            #pragma unroll
            for (int mf = 0; mf < MFRAG; mf++)
                ldsm4(a[mf][0], a[mf][1], a[mf][2], a[mf][3],
                      saH + (u32)(wm + mf * 16 + (lane & 15)) * PA
                          + s * 32 + ((lane >> 4) << 4));
            #pragma unroll
            for (int mf = 0; mf < MFRAG; mf++)
                #pragma unroll
                for (int nf = 0; nf < NFRAG; nf++) {
                    mma_bf16(acc[mf][nf], a[mf], wh[nf]);
                    mma_bf16(acc[mf][nf], a[mf], wl[nf]);
                }
            #pragma unroll
            for (int mf = 0; mf < MFRAG; mf++)
                ldsm4(a[mf][0], a[mf][1], a[mf][2], a[mf][3],
                      saL + (u32)(wm + mf * 16 + (lane & 15)) * PA
                          + s * 32 + ((lane >> 4) << 4));
            #pragma unroll
            for (int mf = 0; mf < MFRAG; mf++)
                #pragma unroll
                for (int nf = 0; nf < NFRAG; nf++)
                    mma_bf16(acc[mf][nf], a[mf], wh[nf]);
        }
        __syncthreads();
    }

    #pragma unroll
    for (int mf = 0; mf < MFRAG; mf++) {
        #pragma unroll
        for (int nf = 0; nf < NFRAG; nf++) {
            const int r0 = bm + wm + mf * 16 + (lane >> 2);
            const int col = bn + wn + nf * 8 + (lane & 3) * 2;
            const float b0 = bias[col], b1 = bias[col + 1];
            *(float2*)&C[(size_t)r0 * ldc + cofs + col] =
                make_float2(acc[mf][nf][0] + b0, acc[mf][nf][1] + b1);
            *(float2*)&C[(size_t)(r0 + 8) * ldc + cofs + col] =
                make_float2(acc[mf][nf][2] + b0, acc[mf][nf][3] + b1);
        }
    }
}

// ---------------------------------------------------------------------------
// Tensor-core LSTM (R9, proven) — outputs written as bf16 hi/lo planes.
// ---------------------------------------------------------------------------
template<int HU, int KLO, bool SEQ>
__global__ __launch_bounds__(512, 1)
void lstm_tc(const float* __restrict__ xz, size_t strideB, size_t strideT,
             const float* __restrict__ Uf, const float* __restrict__ Ub,
             bf16* __restrict__ ohi, bf16* __restrict__ olo, int ldo, int T)
{
    constexpr int NG = 4 * HU, NW = NG / 16, NFRAG = NW / 8;
    constexpr int KF = HU / 16, NFG = NG / 8;
    constexpr int HP = HU + 8;
    constexpr int GP = NG + 4;
    constexpr int NC = HU / 32;

    extern __shared__ char sm[];
    u64*    Uhi  = (u64*)sm;
    u64*    Ulo  = Uhi + KF * NFG * 32;
    __half* hhi  = (__half*)(Ulo + KLO * NFG * 32);
    __half* hlo  = hhi + 16 * HP;
    float*  gbuf = (float*)(hlo + 16 * HP);

    const int tid = threadIdx.x, wid = tid >> 5, lane = tid & 31;
    const int g = lane >> 2, c2 = (lane & 3) * 2;
    const int dir = blockIdx.y, b0 = blockIdx.x * 16;
    const float* U   = dir ? Ub : Uf;
    const float* xzd = xz + (size_t)dir * NG;
    bf16* ohid = ohi + dir * HU;
    bf16* olid = olo + dir * HU;

    for (int idx = tid; idx < KF * NFG * 32; idx += 512) {
        int ln = idx & 31, fr = idx >> 5;
        int nfg = fr % NFG, kf = fr / NFG;
        int n = nfg * 8 + (ln >> 2);
        int k0 = kf * 16 + 2 * (ln & 3);
        float x0 = U[(size_t)k0 * NG + n],       x1 = U[(size_t)(k0 + 1) * NG + n];
        float x2 = U[(size_t)(k0 + 8) * NG + n], x3 = U[(size_t)(k0 + 9) * NG + n];
        Uhi[idx] = pkh64(__half2float(__float2half_rn(x0)),
                         __half2float(__float2half_rn(x1)),
                         __half2float(__float2half_rn(x2)),
                         __half2float(__float2half_rn(x3)));
        if (kf < KLO)
            Ulo[(size_t)(kf * NFG + nfg) * 32 + ln] =
                pkh64(hres(x0), hres(x1), hres(x2), hres(x3));
    }
    for (int idx = tid; idx < 16 * HP / 2; idx += 512) {
        ((u32*)hhi)[idx] = 0; ((u32*)hlo)[idx] = 0;
    }
    __syncthreads();

    const int gate = (wid * NW) / HU;
    const int ur = tid >> 5, uj = (tid & 31) * NC;
    float cst[NC];
    #pragma unroll
    for (int i = 0; i < NC; i++) cst[i] = 0.f;

    for (int t = 0; t < T; t++) {
        const int tt = dir ? (T - 1 - t) : t;

        float xv[NFRAG][4];
        {
            const float* xp0 = xzd + (size_t)(b0 + g) * strideB
                               + (size_t)tt * strideT + wid * NW + c2;
            const float* xp1 = xp0 + 8 * strideB;
            #pragma unroll
            for (int nf = 0; nf < NFRAG; nf++) {
                float2 v0 = *(const float2*)(xp0 + nf * 8);
                float2 v1 = *(const float2*)(xp1 + nf * 8);
                xv[nf][0] = v0.x; xv[nf][1] = v0.y;
                xv[nf][2] = v1.x; xv[nf][3] = v1.y;
            }
        }

        float acc[NFRAG][4];
        #pragma unroll
        for (int nf = 0; nf < NFRAG; nf++)
            #pragma unroll
            for (int q = 0; q < 4; q++) acc[nf][q] = 0.f;

        #pragma unroll
        for (int kf = 0; kf < KF; kf++) {
            const int kb = kf * 16 + c2;
            u32 a[4], al[4];
            a[0]  = *(u32*)&hhi[g * HP + kb];       a[1]  = *(u32*)&hhi[(g + 8) * HP + kb];
            a[2]  = *(u32*)&hhi[g * HP + kb + 8];   a[3]  = *(u32*)&hhi[(g + 8) * HP + kb + 8];
            al[0] = *(u32*)&hlo[g * HP + kb];       al[1] = *(u32*)&hlo[(g + 8) * HP + kb];
            al[2] = *(u32*)&hlo[g * HP + kb + 8];   al[3] = *(u32*)&hlo[(g + 8) * HP + kb + 8];
            const u64* ub = Uhi + ((size_t)kf * NFG + wid * NFRAG) * 32 + lane;
            #pragma unroll
            for (int nf = 0; nf < NFRAG; nf++) {
                u64 b = ub[nf * 32];
                mma_f16(acc[nf], a,  (u32)b, (u32)(b >> 32));
                mma_f16(acc[nf], al, (u32)b, (u32)(b >> 32));
            }
            if (kf < KLO) {
                const u64* lb = Ulo + ((size_t)kf * NFG + wid * NFRAG) * 32 + lane;
                #pragma unroll
                for (int nf = 0; nf < NFRAG; nf++) {
                    u64 b = lb[nf * 32];
                    mma_f16(acc[nf], a, (u32)b, (u32)(b >> 32));
                }
            }
        }

        #pragma unroll
        for (int nf = 0; nf < NFRAG; nf++) {
            const int n = wid * NW + nf * 8 + c2;
            float z0 = acc[nf][0] + xv[nf][0], z1 = acc[nf][1] + xv[nf][1];
            float z2 = acc[nf][2] + xv[nf][2], z3 = acc[nf][3] + xv[nf][3];
            float2 w0, w1;
            if (gate == 2) {
                w0 = make_float2(fmaxf(z0, 0.f), fmaxf(z1, 0.f));
                w1 = make_float2(fmaxf(z2, 0.f), fmaxf(z3, 0.f));
            } else {
                w0 = make_float2(sigm(z0), sigm(z1));
                w1 = make_float2(sigm(z2), sigm(z3));
            }
            *(float2*)&gbuf[g * GP + n]       = w0;
            *(float2*)&gbuf[(g + 8) * GP + n] = w1;
        }
        __syncthreads();

        {
            float iv[NC], fv[NC], gv[NC], ov[NC], ho[NC];
            const float* gb = gbuf + ur * GP + uj;
            if constexpr (NC == 4) {
                *(float4*)iv = *(const float4*)(gb);
                *(float4*)fv = *(const float4*)(gb + HU);
                *(float4*)gv = *(const float4*)(gb + 2 * HU);
                *(float4*)ov = *(const float4*)(gb + 3 * HU);
            } else {
                *(float2*)iv = *(const float2*)(gb);
                *(float2*)fv = *(const float2*)(gb + HU);
                *(float2*)gv = *(const float2*)(gb + 2 * HU);
                *(float2*)ov = *(const float2*)(gb + 3 * HU);
            }
            #pragma unroll
            for (int i = 0; i < NC; i++) {
                cst[i] = fv[i] * cst[i] + iv[i] * gv[i];
                ho[i] = ov[i] * fmaxf(cst[i], 0.f);
            }
            if (SEQ || t == T - 1) {
                size_t idx = SEQ ? (((size_t)(b0 + ur) * T + tt) * ldo + uj)
                                 : ((size_t)(b0 + ur) * ldo + uj);
                u32 hw0 = pkbf(ho[0], ho[1]);
                u32 lw0 = pkbf(bres(ho[0]), bres(ho[1]));
                if constexpr (NC == 4) {
                    u32 hw1 = pkbf(ho[2], ho[3]);
                    u32 lw1 = pkbf(bres(ho[2]), bres(ho[3]));
                    *(uint2*)(ohid + idx) = make_uint2(hw0, hw1);
                    *(uint2*)(olid + idx) = make_uint2(lw0, lw1);
                } else {
                    *(u32*)(ohid + idx) = hw0;
                    *(u32*)(olid + idx) = lw0;
                }
            }
            u32 hw[NC / 2], lw[NC / 2];
            #pragma unroll
            for (int q = 0; q < NC / 2; q++) {
                float a0 = ho[2 * q], a1 = ho[2 * q + 1];
                float p0 = __half2float(__float2half_rn(a0));
                float p1 = __half2float(__float2half_rn(a1));
                hw[q] = pkh2(p0, p1);
                lw[q] = pkh2(a0 - p0, a1 - p1);
            }
            u32* hp = (u32*)&hhi[ur * HP + uj];
            u32* lp = (u32*)&hlo[ur * HP + uj];
            if constexpr (NC == 4) {
                *(uint2*)hp = make_uint2(hw[0], hw[1]);
                *(uint2*)lp = make_uint2(lw[0], lw[1]);
            } else {
                hp[0] = hw[0]; lp[0] = lw[0];
            }
        }
        __syncthreads();
    }
}

// ---------------------------------------------------------------------------
extern "C" void kernel_launch(void* const* d_in, const int* in_sizes, int n_in,
                              void* d_out, int out_size)
{
    const float* x    = (const float*)d_in[0];
    const float* e1fW = (const float*)d_in[1];
    const float* e1fU = (const float*)d_in[2];
    const float* e1fb = (const float*)d_in[3];
    const float* e1bW = (const float*)d_in[4];
    const float* e1bU = (const float*)d_in[5];
    const float* e1bb = (const float*)d_in[6];
    const float* e2fW = (const float*)d_in[7];
    const float* e2fU = (const float*)d_in[8];
    const float* e2fb = (const float*)d_in[9];
    const float* e2bW = (const float*)d_in[10];
    const float* e2bU = (const float*)d_in[11];
    const float* e2bb = (const float*)d_in[12];
    const float* d1fW = (const float*)d_in[13];
    const float* d1fU = (const float*)d_in[14];
    const float* d1fb = (const float*)d_in[15];
    const float* d1bW = (const float*)d_in[16];
    const float* d1bU = (const float*)d_in[17];
    const float* d1bb = (const float*)d_in[18];
    const float* d2fW = (const float*)d_in[19];
    const float* d2fU = (const float*)d_in[20];
    const float* d2fb = (const float*)d_in[21];
    const float* d2bW = (const float*)d_in[22];
    const float* d2bU = (const float*)d_in[23];
    const float* d2bb = (const float*)d_in[24];
    const float* Wd   = (const float*)d_in[25];
    const float* bd   = (const float*)d_in[26];

    float *xz1, *xz2, *xzd1;
    bf16 *xhi, *xlo, *h1hi, *h1lo, *hd1hi, *hd1lo, *zhi, *zlo, *whi, *wlo;
    cudaGetSymbolAddress((void**)&xz1,   g_xz1);
    cudaGetSymbolAddress((void**)&xz2,   g_xz2);
    cudaGetSymbolAddress((void**)&xzd1,  g_xzd1);
    cudaGetSymbolAddress((void**)&xhi,   g_xhi);
    cudaGetSymbolAddress((void**)&xlo,   g_xlo);
    cudaGetSymbolAddress((void**)&h1hi,  g_h1hi);
    cudaGetSymbolAddress((void**)&h1lo,  g_h1lo);
    cudaGetSymbolAddress((void**)&hd1hi, g_hd1hi);
    cudaGetSymbolAddress((void**)&hd1lo, g_hd1lo);
    cudaGetSymbolAddress((void**)&zhi,   g_zhi);
    cudaGetSymbolAddress((void**)&zlo,   g_zlo);
    cudaGetSymbolAddress((void**)&whi,   g_whi);
    cudaGetSymbolAddress((void**)&wlo,   g_wlo);

    const int O_e1f = 0,      O_e1b = 32768,  O_e2f = 65536,  O_e2b = 131072;
    const int O_d1f = 196608, O_d1b = 229376, O_d2f = 262144, O_d2b = 327680;
    const int O_wd  = 393216;

    const int LS128 = 205568, LS64 = 86784;
    cudaFuncSetAttribute(lstm_tc<128, 2, true>,
                         cudaFuncAttributeMaxDynamicSharedMemorySize, LS128);
    cudaFuncSetAttribute(lstm_tc<64, 4, false>,
                         cudaFuncAttributeMaxDynamicSharedMemorySize, LS64);
    cudaFuncSetAttribute(lstm_tc<64, 4, true>,
                         cudaFuncAttributeMaxDynamicSharedMemorySize, LS64);

    // gemm smem: PA=80 -> ASZ=10240; GS128 = 2*(2*10240+2*32*272) = 75776
    //            GS64  = 2*(2*10240+2*32*144) = 59392
    const int GS128 = 2 * (2 * 128 * 80 + 2 * 32 * 272);
    const int GS64  = 2 * (2 * 128 * 80 + 2 * 32 * 144);
    cudaFuncSetAttribute(hgemm2<128, 2, 4>,
                         cudaFuncAttributeMaxDynamicSharedMemorySize, GS128);
    cudaFuncSetAttribute(hgemm2<64, 4, 2>,
                         cudaFuncAttributeMaxDynamicSharedMemorySize, GS64);

    const int T = 256;

    cvt_x<<<2048, 256>>>(x, xhi, xlo, 2097152);
    cvt_w9<<<256, 256>>>(e1fW, e1bW, e2fW, e2bW, d1fW, d1bW, d2fW, d2bW, Wd,
                         whi, wlo);

    // e1 (K=64, Nw=512, both dirs)
    hgemm2<128, 2, 4><<<dim3(4, 1024, 2), 256, GS128>>>(
        xhi, xlo, whi + O_e1f, wlo + O_e1f, whi + O_e1b, wlo + O_e1b,
        e1fb, e1bb, xz1, 64, 512, 1024, 512);
    lstm_tc<128, 2, true><<<dim3(32, 2), 512, LS128>>>(
        xz1, (size_t)T * 1024, 1024, e1fU, e1bU, h1hi, h1lo, 256, T);

    // e2 (K=256, Nw=256)
    hgemm2<128, 2, 4><<<dim3(2, 1024, 2), 256, GS128>>>(
        h1hi, h1lo, whi + O_e2f, wlo + O_e2f, whi + O_e2b, wlo + O_e2b,
        e2fb, e2bb, xz2, 256, 256, 512, 256);
    lstm_tc<64, 4, false><<<dim3(32, 2), 512, LS64>>>(
        xz2, (size_t)T * 512, 512, e2fU, e2bU, zhi, zlo, 128, T);

    // d1 (M=512, K=128, Nw=256)
    hgemm2<128, 2, 4><<<dim3(2, 4, 2), 256, GS128>>>(
        zhi, zlo, whi + O_d1f, wlo + O_d1f, whi + O_d1b, wlo + O_d1b,
        d1fb, d1bb, xzd1, 128, 256, 512, 256);
    lstm_tc<64, 4, true><<<dim3(32, 2), 512, LS64>>>(
        xzd1, 512, 0, d1fU, d1bU, hd1hi, hd1lo, 128, T);

    // d2 (K=128, Nw=512)
    hgemm2<128, 2, 4><<<dim3(4, 1024, 2), 256, GS128>>>(
        hd1hi, hd1lo, whi + O_d2f, wlo + O_d2f, whi + O_d2b, wlo + O_d2b,
        d2fb, d2bb, xz1, 128, 512, 1024, 512);
    lstm_tc<128, 2, true><<<dim3(32, 2), 512, LS128>>>(
        xz1, (size_t)T * 1024, 1024, d2fU, d2bU, h1hi, h1lo, 256, T);

    // dense (K=256, Nw=64, single dir)
    hgemm2<64, 4, 2><<<dim3(1, 1024, 1), 256, GS64>>>(
        h1hi, h1lo, whi + O_wd, wlo + O_wd, whi + O_wd, wlo + O_wd,
        bd, bd, (float*)d_out, 256, 64, 64, 0);
}